// round 14
// baseline (speedup 1.0000x reference)
#include <cuda_runtime.h>
#include <cuda_fp16.h>
#include <math.h>
#include <stdint.h>

// Problem constants
#define BATCH 2
#define SEQ   2048
#define DMODEL 1024
#define NHEAD 16
#define DHEAD 64
#define DFF   4096
#define ROWS  (BATCH*SEQ)   // 4096

// ----------------------------------------------------------------------------
// Scratch (device globals; no allocations allowed)
// ----------------------------------------------------------------------------
__device__ __half g_h   [(size_t)ROWS*DMODEL];
__device__ __half g_q   [(size_t)ROWS*DMODEL];
__device__ __half g_k   [(size_t)ROWS*DMODEL];
__device__ __half g_v   [(size_t)ROWS*DMODEL];
__device__ __half g_ctx [(size_t)ROWS*DMODEL];
__device__ float  g_x2  [(size_t)ROWS*DMODEL];
__device__ __half g_ffn [(size_t)ROWS*DFF];
__device__ float  g_cos [SEQ*32];
__device__ float  g_sin [SEQ*32];
// fp16 weights
__device__ __half g_wqh [(size_t)DMODEL*DMODEL];
__device__ __half g_wkh [(size_t)DMODEL*DMODEL];
__device__ __half g_wvh [(size_t)DMODEL*DMODEL];
__device__ __half g_woh [(size_t)DMODEL*DMODEL];
__device__ __half g_w1h [(size_t)2*DFF*DMODEL];   // row-permuted u1/u2 interleaved
__device__ __half g_w2h [(size_t)DMODEL*DFF];

// ----------------------------------------------------------------------------
// Helpers
// ----------------------------------------------------------------------------
__device__ __forceinline__ uint32_t smem_u32(const void* p) {
    uint32_t a;
    asm("{ .reg .u64 t; cvta.to.shared.u64 t, %1; cvt.u32.u64 %0, t; }" : "=r"(a) : "l"(p));
    return a;
}
__device__ __forceinline__ void cp16(uint32_t dst, const void* src) {
    asm volatile("cp.async.ca.shared.global [%0], [%1], 16;" :: "r"(dst), "l"(src) : "memory");
}
#define CP_COMMIT() asm volatile("cp.async.commit_group;" ::: "memory")
#define CP_WAIT1()  asm volatile("cp.async.wait_group 1;" ::: "memory")
#define CP_WAIT0()  asm volatile("cp.async.wait_group 0;" ::: "memory")

// fp16 mma, fp32 accumulate: m16n8k16
__device__ __forceinline__ void mma_f16(float* c, const uint32_t* a, uint32_t b0, uint32_t b1) {
    asm volatile("mma.sync.aligned.m16n8k16.row.col.f32.f16.f16.f32 "
                 "{%0,%1,%2,%3}, {%4,%5,%6,%7}, {%8,%9}, {%0,%1,%2,%3};"
                 : "+f"(c[0]), "+f"(c[1]), "+f"(c[2]), "+f"(c[3])
                 : "r"(a[0]), "r"(a[1]), "r"(a[2]), "r"(a[3]), "r"(b0), "r"(b1));
}
__device__ __forceinline__ void ldsm4(uint32_t* r, uint32_t addr) {
    asm volatile("ldmatrix.sync.aligned.m8n8.x4.shared.b16 {%0,%1,%2,%3}, [%4];"
                 : "=r"(r[0]), "=r"(r[1]), "=r"(r[2]), "=r"(r[3]) : "r"(addr));
}
__device__ __forceinline__ void ldsm4t(uint32_t* r, uint32_t addr) {
    asm volatile("ldmatrix.sync.aligned.m8n8.x4.trans.shared.b16 {%0,%1,%2,%3}, [%4];"
                 : "=r"(r[0]), "=r"(r[1]), "=r"(r[2]), "=r"(r[3]) : "r"(addr));
}

// ----------------------------------------------------------------------------
// RoPE table
// ----------------------------------------------------------------------------
__global__ void build_rope_table() {
    int idx = blockIdx.x * blockDim.x + threadIdx.x;
    if (idx >= SEQ * 32) return;
    int s = idx / 32, j = idx % 32;
    double invf = exp(-(double)j * (9.210340371976184 / 32.0));
    double a = (double)s * invf;
    g_cos[idx] = (float)cos(a);
    g_sin[idx] = (float)sin(a);
}

// ----------------------------------------------------------------------------
// fp32 -> fp16 weight conversion (plain, and w1 permute variant)
// ----------------------------------------------------------------------------
__global__ __launch_bounds__(256) void cvt_half(const float2* __restrict__ in,
                                                __half2* __restrict__ out, int n2) {
    int i = blockIdx.x * 256 + threadIdx.x;
    if (i >= n2) return;
    out[i] = __float22half2_rn(in[i]);
}
// dst row 2j <- src j (u1), dst row 2j+1 <- src DFF+j (u2)
__global__ __launch_bounds__(256) void cvt_w1(const float2* __restrict__ in,
                                              __half2* __restrict__ out) {
    int i = blockIdx.x * 256 + threadIdx.x;
    const int C2 = DMODEL / 2;
    if (i >= 2 * DFF * C2) return;
    int row = i / C2, c = i % C2;
    int src = (row & 1) ? (DFF + (row >> 1)) : (row >> 1);
    out[i] = __float22half2_rn(in[(size_t)src * C2 + c]);
}

// ----------------------------------------------------------------------------
// RMSNorm -> half output
// ----------------------------------------------------------------------------
__global__ __launch_bounds__(256) void rmsnorm_k(const float* __restrict__ x,
                                                 const float* __restrict__ g,
                                                 __half* __restrict__ o) {
    int row = blockIdx.x;
    const float* xr = x + (size_t)row * DMODEL;
    float ss = 0.f;
    for (int c = threadIdx.x; c < DMODEL; c += 256) { float v = xr[c]; ss += v * v; }
    __shared__ float sm[8];
    for (int off = 16; off; off >>= 1) ss += __shfl_down_sync(0xffffffffu, ss, off);
    if ((threadIdx.x & 31) == 0) sm[threadIdx.x >> 5] = ss;
    __syncthreads();
    if (threadIdx.x < 8) {
        float v = sm[threadIdx.x];
        for (int off = 4; off; off >>= 1) v += __shfl_down_sync(0xffu, v, off);
        if (threadIdx.x == 0) sm[0] = v;
    }
    __syncthreads();
    float inv = 1.0f / sqrtf(sm[0] / (float)DMODEL + 1e-6f);
    __half* orow = o + (size_t)row * DMODEL;
    for (int c = threadIdx.x; c < DMODEL; c += 256)
        orow[c] = __float2half_rn(xr[c] * inv * g[c]);
}

// ----------------------------------------------------------------------------
// FP16 mma.sync GEMM. BM=128 BN=256 BK=32(halves), 3-stage cp.async.
// 256 threads = 8 warps, warp grid 2m x 4n, warp tile 64x64.
// MODE 0: fp32 store (+res). MODE 3: SwiGLU half out. MODE 4: fused QKV half out.
// ----------------------------------------------------------------------------
#define BK 32
#define LDTH 40                          // halves per row (80 bytes)
#define STG_A (128*LDTH)                 // halves
#define STG_B (256*LDTH)
#define STG_T (STG_A+STG_B)              // 15360 halves = 30720 bytes
#define GSTAGES 3
#define GEMM_SMEM (GSTAGES*STG_T*2)      // 92160 bytes

template<int MODE>
__global__ void __launch_bounds__(256, 1) gemm_mma(
    const __half* __restrict__ A, const __half* __restrict__ B,
    const __half* __restrict__ B2, const __half* __restrict__ B3,
    const float* __restrict__ res, void* __restrict__ Cv0,
    void* __restrict__ Cv1, void* __restrict__ Cv2,
    int M, int N, int K)
{
    extern __shared__ char smc[];
    const uint32_t ssu = smem_u32(smc);

    const int tid = threadIdx.x;
    const int wid = tid >> 5, lane = tid & 31;
    const int wm = wid & 1, wn = wid >> 1;
    const int g = lane >> 2, tg = lane & 3;
    const int m0 = blockIdx.y * 128, n0 = blockIdx.x * 256;

    // A loader: 128 rows x 4 chunks(16B) = 512 cps; 2 per thread.
    const int arow = tid >> 1, achk = (tid & 1) * 2;
    const __half* APtr[2];
#pragma unroll
    for (int it = 0; it < 2; it++)
        APtr[it] = A + (size_t)(m0 + arow) * K + (achk + it) * 8;

    // B loader: 256 rows x 4 chunks(16B) = 1024 cps; 4 per thread.
    // row = (tid>>1) + rt*128 (rt 0/1); chunk = (tid&1)*2 + jt (jt 0/1).
    const int brow = tid >> 1, bchk = (tid & 1) * 2;
    const __half* BPtr[4];
    {
        const __half* W = B;
        int nbase = n0;
        if (MODE == 4) {
            int region = n0 >> 10; nbase = n0 & 1023;
            W = (region == 0) ? B : (region == 1) ? B2 : B3;
        }
#pragma unroll
        for (int rt = 0; rt < 2; rt++)
#pragma unroll
            for (int jt = 0; jt < 2; jt++)
                BPtr[rt * 2 + jt] = W + (size_t)(nbase + brow + rt * 128) * K
                                      + (bchk + jt) * 8;
    }

    const uint32_t stAoff = ssu + (arow * LDTH + achk * 8) * 2;
    const uint32_t stBoff = ssu + STG_A * 2 + (brow * LDTH + bchk * 8) * 2;

    const int niter = K >> 5;

    // prologue: stages 0,1
#pragma unroll
    for (int s = 0; s < 2; s++) {
        uint32_t off = s * STG_T * 2;
        int ko = s * BK;
#pragma unroll
        for (int it = 0; it < 2; it++)
            cp16(stAoff + off + it * 16, APtr[it] + ko);
#pragma unroll
        for (int rt = 0; rt < 2; rt++)
#pragma unroll
            for (int jt = 0; jt < 2; jt++)
                cp16(stBoff + off + rt * 128 * LDTH * 2 + jt * 16,
                     BPtr[rt * 2 + jt] + ko);
        CP_COMMIT();
    }

    float c[4][8][4] = {};

    const int r15 = lane & 15;
    const int ch16 = (lane >> 4) << 4;   // bytes
    const uint32_t aAddr0 = (uint32_t)((wm * 64 + r15) * LDTH * 2 + ch16);
    const uint32_t bAddr0 = (uint32_t)(STG_A * 2 + (wn * 64 + r15) * LDTH * 2 + ch16);

    int bufc = 0;
    for (int i = 0; i < niter; i++) {
        CP_WAIT1();
        __syncthreads();

        int nb = i + 2;
        if (nb < niter) {
            int bufn = bufc + 2; if (bufn >= 3) bufn -= 3;
            uint32_t off = bufn * STG_T * 2;
            int ko = nb * BK;
#pragma unroll
            for (int it = 0; it < 2; it++)
                cp16(stAoff + off + it * 16, APtr[it] + ko);
#pragma unroll
            for (int rt = 0; rt < 2; rt++)
#pragma unroll
                for (int jt = 0; jt < 2; jt++)
                    cp16(stBoff + off + rt * 128 * LDTH * 2 + jt * 16,
                         BPtr[rt * 2 + jt] + ko);
        }
        CP_COMMIT();

        const uint32_t stA = ssu + bufc * STG_T * 2 + aAddr0;
        const uint32_t stB = ssu + bufc * STG_T * 2 + bAddr0;
#pragma unroll
        for (int ks = 0; ks < 2; ks++) {   // k16 steps
            uint32_t af[4][4], bf[4][4];
#pragma unroll
            for (int mi = 0; mi < 4; mi++)
                ldsm4(af[mi], stA + mi * 16 * LDTH * 2 + ks * 32);
#pragma unroll
            for (int grp = 0; grp < 4; grp++)
                ldsm4(bf[grp], stB + grp * 16 * LDTH * 2 + ks * 32);
#pragma unroll
            for (int mi = 0; mi < 4; mi++)
#pragma unroll
                for (int ni = 0; ni < 8; ni++) {
                    int grp = ni >> 1, odd = ni & 1;
                    mma_f16(c[mi][ni], af[mi], bf[grp][odd], bf[grp][2 + odd]);
                }
        }
        if (++bufc == 3) bufc = 0;
    }

    // ---------------- epilogues ----------------
    if (MODE == 0) {
        float* C = (float*)Cv0;
#pragma unroll
        for (int mi = 0; mi < 4; mi++) {
            int r = m0 + wm * 64 + mi * 16 + g;
#pragma unroll
            for (int ni = 0; ni < 8; ni++) {
                int cc = n0 + wn * 64 + ni * 8 + tg * 2;
                size_t o1 = (size_t)r * N + cc;
                size_t o2 = (size_t)(r + 8) * N + cc;
                float2 v1 = make_float2(c[mi][ni][0], c[mi][ni][1]);
                float2 v2 = make_float2(c[mi][ni][2], c[mi][ni][3]);
                if (res) {
                    float2 r1 = *reinterpret_cast<const float2*>(res + o1);
                    float2 r2 = *reinterpret_cast<const float2*>(res + o2);
                    v1.x += r1.x; v1.y += r1.y; v2.x += r2.x; v2.y += r2.y;
                }
                *reinterpret_cast<float2*>(C + o1) = v1;
                *reinterpret_cast<float2*>(C + o2) = v2;
            }
        }
    } else if (MODE == 4) {
        int region = n0 >> 10, nloc = n0 & 1023;
        __half* OUT = (region == 0) ? (__half*)Cv0 : (region == 1) ? (__half*)Cv1 : (__half*)Cv2;
        int h = (nloc + wn * 64) >> 6;
        bool doRope = (region < 2);
#pragma unroll
        for (int mi = 0; mi < 4; mi++) {
#pragma unroll
            for (int half_ = 0; half_ < 2; half_++) {
                int r = m0 + wm * 64 + mi * 16 + g + half_ * 8;
                int bb = r >> 11, s = r & 2047;
                size_t base = (((size_t)(bb * NHEAD + h)) * SEQ + s) * 64;
                if (!doRope) {
#pragma unroll
                    for (int ni = 0; ni < 8; ni++) {
                        __half2 v = __floats2half2_rn(c[mi][ni][half_*2], c[mi][ni][half_*2+1]);
                        *reinterpret_cast<__half2*>(OUT + base + ni * 8 + tg * 2) = v;
                    }
                } else {
#pragma unroll
                    for (int ni = 0; ni < 4; ni++) {
                        int dk0 = ni * 8 + tg * 2;
                        float o1x, o1y, o2x, o2y;
#pragma unroll
                        for (int j = 0; j < 2; j++) {
                            int dk = dk0 + j;
                            float x1 = c[mi][ni][half_*2 + j];
                            float x2 = c[mi][ni+4][half_*2 + j];
                            float cs = g_cos[s * 32 + dk];
                            float sn = g_sin[s * 32 + dk];
                            float v1 = x1 * cs - x2 * sn;
                            float v2 = x2 * cs + x1 * sn;
                            if (j == 0) { o1x = v1; o2x = v2; }
                            else        { o1y = v1; o2y = v2; }
                        }
                        *reinterpret_cast<__half2*>(OUT + base + dk0)      = __floats2half2_rn(o1x, o1y);
                        *reinterpret_cast<__half2*>(OUT + base + dk0 + 32) = __floats2half2_rn(o2x, o2y);
                    }
                }
            }
        }
    } else {  // MODE 3: SwiGLU — half output width N/2 (w1 pre-permuted)
        __half* C = (__half*)Cv0;
        const int NO = N >> 1;
#pragma unroll
        for (int mi = 0; mi < 4; mi++) {
            int r = m0 + wm * 64 + mi * 16 + g;
#pragma unroll
            for (int ni = 0; ni < 8; ni++) {
                int oc = (n0 + wn * 64 + ni * 8) / 2 + tg;
                float u1a = c[mi][ni][0], u2a = c[mi][ni][1];
                float u1b = c[mi][ni][2], u2b = c[mi][ni][3];
                C[(size_t)r * NO + oc]       = __float2half_rn(u1a * (u2a / (1.0f + expf(-u2a))));
                C[(size_t)(r + 8) * NO + oc] = __float2half_rn(u1b * (u2b / (1.0f + expf(-u2b))));
            }
        }
    }
}

// ----------------------------------------------------------------------------
// Flash attention fp16 (m16n8k16), causal, 64x64 tiles, register softmax.
// Half tiles LD=72 halves (144B rows, conflict-free for ldmatrix).
// ----------------------------------------------------------------------------
#define LDH 72
#define TIH (64*LDH)          // 4608 halves = 9216 bytes
#define FA_SMEM (6*TIH*2 + 1536)

__global__ void __launch_bounds__(256, 2) flash_attn_tc(
    const __half* __restrict__ Q, const __half* __restrict__ Kg,
    const __half* __restrict__ Vg, __half* __restrict__ ctx)
{
    extern __shared__ char fsc[];
    __half* Qs = (__half*)fsc;
    __half* Ks = (__half*)(fsc + TIH*2);
    __half* Vs = (__half*)(fsc + 3*TIH*2);
    __half* Ps = (__half*)(fsc + 5*TIH*2);
    float* rowm  = (float*)(fsc + 6*TIH*2);
    float* rowl  = rowm + 64;
    float* mpart = rowl + 64;
    float* lpart = mpart + 128;

    const uint32_t qsu = smem_u32(Qs);
    const uint32_t ksu = smem_u32(Ks);
    const uint32_t vsu = smem_u32(Vs);
    const uint32_t psu = smem_u32(Ps);

    const int qt = (int)gridDim.x - 1 - (int)blockIdx.x;
    const int bh = blockIdx.y;
    const int tid = threadIdx.x;
    const int wid = tid >> 5, lane = tid & 31;
    const int wm = wid & 3, wn = wid >> 2;
    const int g = lane >> 2, tg = lane & 3;
    const int r15 = lane & 15;
    const int ch16 = (lane >> 4) << 4;

    const int rA = wm * 16 + g, rB = rA + 8;

    const size_t baseQ = ((size_t)bh * SEQ + (size_t)qt * 64) * DHEAD;
#pragma unroll
    for (int it = 0; it < 2; it++) {
        int idx = tid + it * 256;
        int r = idx >> 3, c8 = (idx & 7) * 8;
        *reinterpret_cast<uint4*>(Qs + r * LDH + c8) =
            *reinterpret_cast<const uint4*>(Q + baseQ + (size_t)r * DHEAD + c8);
    }
    if (tid < 64) { rowm[tid] = -1e30f; rowl[tid] = 0.f; }

    const int ntile = qt + 1;
    const int qbase = qt * 64;

    {
        const __half* Kb = Kg + ((size_t)bh * SEQ) * DHEAD;
        const __half* Vb = Vg + ((size_t)bh * SEQ) * DHEAD;
#pragma unroll
        for (int it = 0; it < 2; it++) {
            int idx = tid + it * 256;
            int r = idx >> 3, c8 = (idx & 7) * 8;
            cp16(ksu + (r * LDH + c8) * 2, Kb + (size_t)r * DHEAD + c8);
            cp16(vsu + (r * LDH + c8) * 2, Vb + (size_t)r * DHEAD + c8);
        }
        CP_COMMIT();
    }

    float co[4][4] = {};

    for (int kt = 0; kt < ntile; kt++) {
        const int buf = kt & 1;
        if (kt + 1 < ntile) {
            const __half* Kb = Kg + ((size_t)bh * SEQ + (size_t)(kt+1) * 64) * DHEAD;
            const __half* Vb = Vg + ((size_t)bh * SEQ + (size_t)(kt+1) * 64) * DHEAD;
            uint32_t kd = ksu + ((buf ^ 1) * TIH) * 2;
            uint32_t vd = vsu + ((buf ^ 1) * TIH) * 2;
#pragma unroll
            for (int it = 0; it < 2; it++) {
                int idx = tid + it * 256;
                int r = idx >> 3, c8 = (idx & 7) * 8;
                cp16(kd + (r * LDH + c8) * 2, Kb + (size_t)r * DHEAD + c8);
                cp16(vd + (r * LDH + c8) * 2, Vb + (size_t)r * DHEAD + c8);
            }
            CP_COMMIT();
            CP_WAIT1();
        } else {
            CP_WAIT0();
        }
        __syncthreads();

        // ---- S = Q @ K^T : 4 k16-steps over d=64 ----
        float cs_[4][4] = {};
        {
            const uint32_t aQ = qsu + ((wm * 16 + r15) * LDH) * 2 + ch16;
            const uint32_t bK = ksu + (buf * TIH + (wn * 32 + r15) * LDH) * 2 + ch16;
#pragma unroll
            for (int ks = 0; ks < 4; ks++) {
                uint32_t qa[4], k0f[4], k1f[4];
                ldsm4(qa, aQ + ks * 32);
                ldsm4(k0f, bK + ks * 32);
                ldsm4(k1f, bK + 16 * LDH * 2 + ks * 32);
                mma_f16(cs_[0], qa, k0f[0], k0f[2]);
                mma_f16(cs_[1], qa, k0f[1], k0f[3]);
                mma_f16(cs_[2], qa, k1f[0], k1f[2]);
                mma_f16(cs_[3], qa, k1f[1], k1f[3]);
            }
        }

        // ---- scale + causal mask in registers ----
#pragma unroll
        for (int ni = 0; ni < 4; ni++)
#pragma unroll
            for (int jj = 0; jj < 4; jj++) cs_[ni][jj] *= 0.125f;
        if (kt == qt) {
#pragma unroll
            for (int ni = 0; ni < 4; ni++) {
                int cloc0 = wn * 32 + ni * 8 + 2 * tg;
                if (cloc0     > rA) cs_[ni][0] = -1e30f;
                if (cloc0 + 1 > rA) cs_[ni][1] = -1e30f;
                if (cloc0     > rB) cs_[ni][2] = -1e30f;
                if (cloc0 + 1 > rB) cs_[ni][3] = -1e30f;
            }
        }

        // ---- warp row max + cross-warp exchange ----
        {
            float mA = -1e30f, mB = -1e30f;
#pragma unroll
            for (int ni = 0; ni < 4; ni++) {
                mA = fmaxf(mA, fmaxf(cs_[ni][0], cs_[ni][1]));
                mB = fmaxf(mB, fmaxf(cs_[ni][2], cs_[ni][3]));
            }
            mA = fmaxf(mA, __shfl_xor_sync(0xffffffffu, mA, 1));
            mA = fmaxf(mA, __shfl_xor_sync(0xffffffffu, mA, 2));
            mB = fmaxf(mB, __shfl_xor_sync(0xffffffffu, mB, 1));
            mB = fmaxf(mB, __shfl_xor_sync(0xffffffffu, mB, 2));
            if (tg == 0) { mpart[wn * 64 + rA] = mA; mpart[wn * 64 + rB] = mB; }
        }
        __syncthreads();

        // ---- exp in registers, half P write, row-sum, local rescale ----
        float mnA, mnB, scA, scB;
        {
            float moA = rowm[rA], moB = rowm[rB];
            mnA = fmaxf(moA, fmaxf(mpart[rA], mpart[64 + rA]));
            mnB = fmaxf(moB, fmaxf(mpart[rB], mpart[64 + rB]));
            scA = __expf(moA - mnA);
            scB = __expf(moB - mnB);
            float lA = 0.f, lB = 0.f;
#pragma unroll
            for (int ni = 0; ni < 4; ni++) {
                int cc = wn * 32 + ni * 8 + 2 * tg;
                float e0 = __expf(cs_[ni][0] - mnA);
                float e1 = __expf(cs_[ni][1] - mnA);
                float e2 = __expf(cs_[ni][2] - mnB);
                float e3 = __expf(cs_[ni][3] - mnB);
                lA += e0 + e1; lB += e2 + e3;
                *reinterpret_cast<__half2*>(Ps + rA * LDH + cc) = __floats2half2_rn(e0, e1);
                *reinterpret_cast<__half2*>(Ps + rB * LDH + cc) = __floats2half2_rn(e2, e3);
            }
            lA += __shfl_xor_sync(0xffffffffu, lA, 1);
            lA += __shfl_xor_sync(0xffffffffu, lA, 2);
            lB += __shfl_xor_sync(0xffffffffu, lB, 1);
            lB += __shfl_xor_sync(0xffffffffu, lB, 2);
            if (tg == 0) { lpart[wn * 64 + rA] = lA; lpart[wn * 64 + rB] = lB; }
#pragma unroll
            for (int ni = 0; ni < 4; ni++) {
                co[ni][0] *= scA; co[ni][1] *= scA;
                co[ni][2] *= scB; co[ni][3] *= scB;
            }
        }
        __syncthreads();

        if (wn == 0 && tg == 0) {
            rowl[rA] = rowl[rA] * scA + lpart[rA] + lpart[64 + rA];
            rowm[rA] = mnA;
            rowl[rB] = rowl[rB] * scB + lpart[rB] + lpart[64 + rB];
            rowm[rB] = mnB;
        }

        // ---- O += P @ V : 4 k16-steps over kv=64; V via trans ldsm ----
        {
            const uint32_t aP = psu + ((wm * 16 + r15) * LDH) * 2 + ch16;
            const uint32_t vB = vsu + (buf * TIH) * 2 + (wn * 32) * 2 + ch16;
#pragma unroll
            for (int ks = 0; ks < 4; ks++) {
                uint32_t pa[4], v0f[4], v1f[4];
                ldsm4(pa, aP + ks * 32);
                uint32_t vrow = vB + ((ks * 16 + r15) * LDH) * 2;
                ldsm4t(v0f, vrow);
                ldsm4t(v1f, vrow + 32);
                mma_f16(co[0], pa, v0f[0], v0f[1]);
                mma_f16(co[1], pa, v0f[2], v0f[3]);
                mma_f16(co[2], pa, v1f[0], v1f[1]);
                mma_f16(co[3], pa, v1f[2], v1f[3]);
            }
        }
        __syncthreads();
    }

    // ---- final write (half) ----
    {
        int b = bh >> 4, h = bh & 15;
        float il_g  = 1.0f / rowl[rA];
        float il_g8 = 1.0f / rowl[rB];
#pragma unroll
        for (int half_ = 0; half_ < 2; half_++) {
            int r = wm * 16 + g + half_ * 8;
            float il = half_ ? il_g8 : il_g;
            size_t grow = ((size_t)b * SEQ + qbase + r) * DMODEL + h * 64;
#pragma unroll
            for (int ni = 0; ni < 4; ni++) {
                int d0 = wn * 32 + ni * 8 + tg * 2;
                *reinterpret_cast<__half2*>(ctx + grow + d0) =
                    __floats2half2_rn(co[ni][half_*2] * il, co[ni][half_*2+1] * il);
            }
        }
    }
}

// ----------------------------------------------------------------------------
// Launch
// ----------------------------------------------------------------------------
extern "C" void kernel_launch(void* const* d_in, const int* in_sizes, int n_in,
                              void* d_out, int out_size) {
    const float* x  = (const float*)d_in[0];
    const float* wq = (const float*)d_in[2];
    const float* wk = (const float*)d_in[3];
    const float* wv = (const float*)d_in[4];
    const float* wo = (const float*)d_in[5];
    const float* w1 = (const float*)d_in[6];
    const float* w2 = (const float*)d_in[7];
    const float* g1 = (const float*)d_in[8];
    const float* g2 = (const float*)d_in[9];
    float* out = (float*)d_out;

    static __half *p_h=nullptr,*p_q=nullptr,*p_k=nullptr,*p_v=nullptr,
                  *p_ctx=nullptr,*p_ffn=nullptr,
                  *p_wqh=nullptr,*p_wkh=nullptr,*p_wvh=nullptr,*p_woh=nullptr,
                  *p_w1h=nullptr,*p_w2h=nullptr;
    static float *p_x2=nullptr;
    if (!p_h) {
        cudaGetSymbolAddress((void**)&p_h,   g_h);
        cudaGetSymbolAddress((void**)&p_q,   g_q);
        cudaGetSymbolAddress((void**)&p_k,   g_k);
        cudaGetSymbolAddress((void**)&p_v,   g_v);
        cudaGetSymbolAddress((void**)&p_ctx, g_ctx);
        cudaGetSymbolAddress((void**)&p_x2,  g_x2);
        cudaGetSymbolAddress((void**)&p_ffn, g_ffn);
        cudaGetSymbolAddress((void**)&p_wqh, g_wqh);
        cudaGetSymbolAddress((void**)&p_wkh, g_wkh);
        cudaGetSymbolAddress((void**)&p_wvh, g_wvh);
        cudaGetSymbolAddress((void**)&p_woh, g_woh);
        cudaGetSymbolAddress((void**)&p_w1h, g_w1h);
        cudaGetSymbolAddress((void**)&p_w2h, g_w2h);
        cudaFuncSetAttribute(gemm_mma<0>, cudaFuncAttributeMaxDynamicSharedMemorySize, GEMM_SMEM);
        cudaFuncSetAttribute(gemm_mma<3>, cudaFuncAttributeMaxDynamicSharedMemorySize, GEMM_SMEM);
        cudaFuncSetAttribute(gemm_mma<4>, cudaFuncAttributeMaxDynamicSharedMemorySize, GEMM_SMEM);
        cudaFuncSetAttribute(flash_attn_tc, cudaFuncAttributeMaxDynamicSharedMemorySize, FA_SMEM);
    }

    build_rope_table<<<(SEQ * 32 + 255) / 256, 256>>>();

    // convert weights to fp16 (w1 permuted)
    const int NW = DMODEL * DMODEL / 2;
    cvt_half<<<(NW + 255)/256, 256>>>((const float2*)wq, (__half2*)p_wqh, NW);
    cvt_half<<<(NW + 255)/256, 256>>>((const float2*)wk, (__half2*)p_wkh, NW);
    cvt_half<<<(NW + 255)/256, 256>>>((const float2*)wv, (__half2*)p_wvh, NW);
    cvt_half<<<(NW + 255)/256, 256>>>((const float2*)wo, (__half2*)p_woh, NW);
    cvt_w1<<<(2*DFF*(DMODEL/2) + 255)/256, 256>>>((const float2*)w1, (__half2*)p_w1h);
    cvt_half<<<(DMODEL*DFF/2 + 255)/256, 256>>>((const float2*)w2, (__half2*)p_w2h, DMODEL*DFF/2);

    // --- attention sublayer ---
    rmsnorm_k<<<ROWS, 256>>>(x, g1, p_h);

    dim3 gqkv(3 * DMODEL / 256, ROWS / 128);   // (12, 32)
    gemm_mma<4><<<gqkv, 256, GEMM_SMEM>>>(p_h, p_wqh, p_wkh, p_wvh, nullptr,
                                          p_q, p_k, p_v, ROWS, 3 * DMODEL, DMODEL);

    flash_attn_tc<<<dim3(SEQ / 64, BATCH * NHEAD), 256, FA_SMEM>>>(p_q, p_k, p_v, p_ctx);

    dim3 gproj(DMODEL / 256, ROWS / 128);      // (4, 32)
    gemm_mma<0><<<gproj, 256, GEMM_SMEM>>>(p_ctx, p_woh, nullptr, nullptr, x,
                                           p_x2, nullptr, nullptr, ROWS, DMODEL, DMODEL);

    // --- FFN sublayer ---
    rmsnorm_k<<<ROWS, 256>>>(p_x2, g2, p_h);
    dim3 gup(2 * DFF / 256, ROWS / 128);       // (32, 32)
    gemm_mma<3><<<gup, 256, GEMM_SMEM>>>(p_h, p_w1h, nullptr, nullptr, nullptr,
                                         p_ffn, nullptr, nullptr, ROWS, 2 * DFF, DMODEL);
    dim3 gdown(DMODEL / 256, ROWS / 128);      // (4, 32)
    gemm_mma<0><<<gdown, 256, GEMM_SMEM>>>(p_ffn, p_w2h, nullptr, nullptr, p_x2,
                                           out, nullptr, nullptr, ROWS, DMODEL, DFF);
}

// round 15
// speedup vs baseline: 1.0485x; 1.0485x over previous
#include <cuda_runtime.h>
#include <cuda_fp16.h>
#include <math.h>
#include <stdint.h>

// Problem constants
#define BATCH 2
#define SEQ   2048
#define DMODEL 1024
#define NHEAD 16
#define DHEAD 64
#define DFF   4096
#define ROWS  (BATCH*SEQ)   // 4096

// ----------------------------------------------------------------------------
// Scratch (device globals; no allocations allowed)
// ----------------------------------------------------------------------------
__device__ __half g_h   [(size_t)ROWS*DMODEL];
__device__ __half g_q   [(size_t)ROWS*DMODEL];
__device__ __half g_k   [(size_t)ROWS*DMODEL];
__device__ __half g_v   [(size_t)ROWS*DMODEL];
__device__ __half g_ctx [(size_t)ROWS*DMODEL];
__device__ float  g_x2  [(size_t)ROWS*DMODEL];
__device__ __half g_ffn [(size_t)ROWS*DFF];
__device__ float  g_cos [SEQ*32];
__device__ float  g_sin [SEQ*32];
// fp16 weights
__device__ __half g_wqh [(size_t)DMODEL*DMODEL];
__device__ __half g_wkh [(size_t)DMODEL*DMODEL];
__device__ __half g_wvh [(size_t)DMODEL*DMODEL];
__device__ __half g_woh [(size_t)DMODEL*DMODEL];
__device__ __half g_w1h [(size_t)2*DFF*DMODEL];   // row-permuted u1/u2 interleaved
__device__ __half g_w2h [(size_t)DMODEL*DFF];

// ----------------------------------------------------------------------------
// Helpers
// ----------------------------------------------------------------------------
__device__ __forceinline__ uint32_t smem_u32(const void* p) {
    uint32_t a;
    asm("{ .reg .u64 t; cvta.to.shared.u64 t, %1; cvt.u32.u64 %0, t; }" : "=r"(a) : "l"(p));
    return a;
}
__device__ __forceinline__ void cp16(uint32_t dst, const void* src) {
    asm volatile("cp.async.ca.shared.global [%0], [%1], 16;" :: "r"(dst), "l"(src) : "memory");
}
#define CP_COMMIT() asm volatile("cp.async.commit_group;" ::: "memory")
#define CP_WAIT1()  asm volatile("cp.async.wait_group 1;" ::: "memory")
#define CP_WAIT0()  asm volatile("cp.async.wait_group 0;" ::: "memory")

// fp16 mma, fp32 accumulate: m16n8k16
__device__ __forceinline__ void mma_f16(float* c, const uint32_t* a, uint32_t b0, uint32_t b1) {
    asm volatile("mma.sync.aligned.m16n8k16.row.col.f32.f16.f16.f32 "
                 "{%0,%1,%2,%3}, {%4,%5,%6,%7}, {%8,%9}, {%0,%1,%2,%3};"
                 : "+f"(c[0]), "+f"(c[1]), "+f"(c[2]), "+f"(c[3])
                 : "r"(a[0]), "r"(a[1]), "r"(a[2]), "r"(a[3]), "r"(b0), "r"(b1));
}
__device__ __forceinline__ void ldsm4(uint32_t* r, uint32_t addr) {
    asm volatile("ldmatrix.sync.aligned.m8n8.x4.shared.b16 {%0,%1,%2,%3}, [%4];"
                 : "=r"(r[0]), "=r"(r[1]), "=r"(r[2]), "=r"(r[3]) : "r"(addr));
}
__device__ __forceinline__ void ldsm4t(uint32_t* r, uint32_t addr) {
    asm volatile("ldmatrix.sync.aligned.m8n8.x4.trans.shared.b16 {%0,%1,%2,%3}, [%4];"
                 : "=r"(r[0]), "=r"(r[1]), "=r"(r[2]), "=r"(r[3]) : "r"(addr));
}
__device__ __forceinline__ uint32_t packh2(float a, float b) {
    __half2 h = __floats2half2_rn(a, b);
    return *reinterpret_cast<uint32_t*>(&h);
}

// ----------------------------------------------------------------------------
// RoPE table
// ----------------------------------------------------------------------------
__global__ void build_rope_table() {
    int idx = blockIdx.x * blockDim.x + threadIdx.x;
    if (idx >= SEQ * 32) return;
    int s = idx / 32, j = idx % 32;
    double invf = exp(-(double)j * (9.210340371976184 / 32.0));
    double a = (double)s * invf;
    g_cos[idx] = (float)cos(a);
    g_sin[idx] = (float)sin(a);
}

// ----------------------------------------------------------------------------
// One-shot weight conversion fp32->fp16 (w1 permuted at the same time)
// ----------------------------------------------------------------------------
#define NW2  (DMODEL*DMODEL/2)       // 524288 half2 per square weight
#define W1_2 (2*DFF*DMODEL/2)        // 4194304
#define W2_2 (DMODEL*DFF/2)          // 2097152
#define CVT_TOTAL (4*NW2 + W1_2 + W2_2)

__global__ __launch_bounds__(256) void cvt_all(
    const float2* __restrict__ wq, const float2* __restrict__ wk,
    const float2* __restrict__ wv, const float2* __restrict__ wo,
    const float2* __restrict__ w1, const float2* __restrict__ w2,
    __half2* __restrict__ oq, __half2* __restrict__ ok,
    __half2* __restrict__ ov, __half2* __restrict__ oo,
    __half2* __restrict__ o1, __half2* __restrict__ o2)
{
    int i = blockIdx.x * 256 + threadIdx.x;
    if (i < 4 * NW2) {
        int w = i / NW2, j = i - w * NW2;
        const float2* src = (w == 0) ? wq : (w == 1) ? wk : (w == 2) ? wv : wo;
        __half2* dst = (w == 0) ? oq : (w == 1) ? ok : (w == 2) ? ov : oo;
        dst[j] = __float22half2_rn(src[j]);
    } else if (i < 4 * NW2 + W1_2) {
        int j = i - 4 * NW2;
        const int C2 = DMODEL / 2;
        int row = j / C2, c = j - row * C2;
        int src = (row & 1) ? (DFF + (row >> 1)) : (row >> 1);
        o1[j] = __float22half2_rn(w1[(size_t)src * C2 + c]);
    } else if (i < CVT_TOTAL) {
        int j = i - 4 * NW2 - W1_2;
        o2[j] = __float22half2_rn(w2[j]);
    }
}

// ----------------------------------------------------------------------------
// RMSNorm -> half output
// ----------------------------------------------------------------------------
__global__ __launch_bounds__(256) void rmsnorm_k(const float* __restrict__ x,
                                                 const float* __restrict__ g,
                                                 __half* __restrict__ o) {
    int row = blockIdx.x;
    const float* xr = x + (size_t)row * DMODEL;
    float ss = 0.f;
    for (int c = threadIdx.x; c < DMODEL; c += 256) { float v = xr[c]; ss += v * v; }
    __shared__ float sm[8];
    for (int off = 16; off; off >>= 1) ss += __shfl_down_sync(0xffffffffu, ss, off);
    if ((threadIdx.x & 31) == 0) sm[threadIdx.x >> 5] = ss;
    __syncthreads();
    if (threadIdx.x < 8) {
        float v = sm[threadIdx.x];
        for (int off = 4; off; off >>= 1) v += __shfl_down_sync(0xffu, v, off);
        if (threadIdx.x == 0) sm[0] = v;
    }
    __syncthreads();
    float inv = 1.0f / sqrtf(sm[0] / (float)DMODEL + 1e-6f);
    __half* orow = o + (size_t)row * DMODEL;
    for (int c = threadIdx.x; c < DMODEL; c += 256)
        orow[c] = __float2half_rn(xr[c] * inv * g[c]);
}

// ----------------------------------------------------------------------------
// FP16 mma.sync GEMM. BM=128 BN=256 BK=32(halves), 3-stage cp.async.
// 256 threads = 8 warps, warp grid 2m x 4n, warp tile 64x64.
// MODE 0: fp32 store (+res). MODE 3: SwiGLU half out. MODE 4: fused QKV half out.
// ----------------------------------------------------------------------------
#define BK 32
#define LDTH 40                          // halves per row (80 bytes)
#define STG_A (128*LDTH)                 // halves
#define STG_B (256*LDTH)
#define STG_T (STG_A+STG_B)              // 15360 halves
#define GSTAGES 3
#define GEMM_SMEM (GSTAGES*STG_T*2)      // 92160 bytes

template<int MODE>
__global__ void __launch_bounds__(256, 1) gemm_mma(
    const __half* __restrict__ A, const __half* __restrict__ B,
    const __half* __restrict__ B2, const __half* __restrict__ B3,
    const float* __restrict__ res, void* __restrict__ Cv0,
    void* __restrict__ Cv1, void* __restrict__ Cv2,
    int M, int N, int K)
{
    extern __shared__ char smc[];
    const uint32_t ssu = smem_u32(smc);

    const int tid = threadIdx.x;
    const int wid = tid >> 5, lane = tid & 31;
    const int wm = wid & 1, wn = wid >> 1;
    const int g = lane >> 2, tg = lane & 3;
    const int m0 = blockIdx.y * 128, n0 = blockIdx.x * 256;

    const int arow = tid >> 1, achk = (tid & 1) * 2;
    const __half* APtr[2];
#pragma unroll
    for (int it = 0; it < 2; it++)
        APtr[it] = A + (size_t)(m0 + arow) * K + (achk + it) * 8;

    const int brow = tid >> 1, bchk = (tid & 1) * 2;
    const __half* BPtr[4];
    {
        const __half* W = B;
        int nbase = n0;
        if (MODE == 4) {
            int region = n0 >> 10; nbase = n0 & 1023;
            W = (region == 0) ? B : (region == 1) ? B2 : B3;
        }
#pragma unroll
        for (int rt = 0; rt < 2; rt++)
#pragma unroll
            for (int jt = 0; jt < 2; jt++)
                BPtr[rt * 2 + jt] = W + (size_t)(nbase + brow + rt * 128) * K
                                      + (bchk + jt) * 8;
    }

    const uint32_t stAoff = ssu + (arow * LDTH + achk * 8) * 2;
    const uint32_t stBoff = ssu + STG_A * 2 + (brow * LDTH + bchk * 8) * 2;

    const int niter = K >> 5;

#pragma unroll
    for (int s = 0; s < 2; s++) {
        uint32_t off = s * STG_T * 2;
        int ko = s * BK;
#pragma unroll
        for (int it = 0; it < 2; it++)
            cp16(stAoff + off + it * 16, APtr[it] + ko);
#pragma unroll
        for (int rt = 0; rt < 2; rt++)
#pragma unroll
            for (int jt = 0; jt < 2; jt++)
                cp16(stBoff + off + rt * 128 * LDTH * 2 + jt * 16,
                     BPtr[rt * 2 + jt] + ko);
        CP_COMMIT();
    }

    float c[4][8][4] = {};

    const int r15 = lane & 15;
    const int ch16 = (lane >> 4) << 4;
    const uint32_t aAddr0 = (uint32_t)((wm * 64 + r15) * LDTH * 2 + ch16);
    const uint32_t bAddr0 = (uint32_t)(STG_A * 2 + (wn * 64 + r15) * LDTH * 2 + ch16);

    int bufc = 0;
    for (int i = 0; i < niter; i++) {
        CP_WAIT1();
        __syncthreads();

        int nb = i + 2;
        if (nb < niter) {
            int bufn = bufc + 2; if (bufn >= 3) bufn -= 3;
            uint32_t off = bufn * STG_T * 2;
            int ko = nb * BK;
#pragma unroll
            for (int it = 0; it < 2; it++)
                cp16(stAoff + off + it * 16, APtr[it] + ko);
#pragma unroll
            for (int rt = 0; rt < 2; rt++)
#pragma unroll
                for (int jt = 0; jt < 2; jt++)
                    cp16(stBoff + off + rt * 128 * LDTH * 2 + jt * 16,
                         BPtr[rt * 2 + jt] + ko);
        }
        CP_COMMIT();

        const uint32_t stA = ssu + bufc * STG_T * 2 + aAddr0;
        const uint32_t stB = ssu + bufc * STG_T * 2 + bAddr0;
#pragma unroll
        for (int ks = 0; ks < 2; ks++) {
            uint32_t af[4][4], bf[4][4];
#pragma unroll
            for (int mi = 0; mi < 4; mi++)
                ldsm4(af[mi], stA + mi * 16 * LDTH * 2 + ks * 32);
#pragma unroll
            for (int grp = 0; grp < 4; grp++)
                ldsm4(bf[grp], stB + grp * 16 * LDTH * 2 + ks * 32);
#pragma unroll
            for (int mi = 0; mi < 4; mi++)
#pragma unroll
                for (int ni = 0; ni < 8; ni++) {
                    int grp = ni >> 1, odd = ni & 1;
                    mma_f16(c[mi][ni], af[mi], bf[grp][odd], bf[grp][2 + odd]);
                }
        }
        if (++bufc == 3) bufc = 0;
    }

    if (MODE == 0) {
        float* C = (float*)Cv0;
#pragma unroll
        for (int mi = 0; mi < 4; mi++) {
            int r = m0 + wm * 64 + mi * 16 + g;
#pragma unroll
            for (int ni = 0; ni < 8; ni++) {
                int cc = n0 + wn * 64 + ni * 8 + tg * 2;
                size_t o1 = (size_t)r * N + cc;
                size_t o2 = (size_t)(r + 8) * N + cc;
                float2 v1 = make_float2(c[mi][ni][0], c[mi][ni][1]);
                float2 v2 = make_float2(c[mi][ni][2], c[mi][ni][3]);
                if (res) {
                    float2 r1 = *reinterpret_cast<const float2*>(res + o1);
                    float2 r2 = *reinterpret_cast<const float2*>(res + o2);
                    v1.x += r1.x; v1.y += r1.y; v2.x += r2.x; v2.y += r2.y;
                }
                *reinterpret_cast<float2*>(C + o1) = v1;
                *reinterpret_cast<float2*>(C + o2) = v2;
            }
        }
    } else if (MODE == 4) {
        int region = n0 >> 10, nloc = n0 & 1023;
        __half* OUT = (region == 0) ? (__half*)Cv0 : (region == 1) ? (__half*)Cv1 : (__half*)Cv2;
        int h = (nloc + wn * 64) >> 6;
        bool doRope = (region < 2);
#pragma unroll
        for (int mi = 0; mi < 4; mi++) {
#pragma unroll
            for (int half_ = 0; half_ < 2; half_++) {
                int r = m0 + wm * 64 + mi * 16 + g + half_ * 8;
                int bb = r >> 11, s = r & 2047;
                size_t base = (((size_t)(bb * NHEAD + h)) * SEQ + s) * 64;
                if (!doRope) {
#pragma unroll
                    for (int ni = 0; ni < 8; ni++) {
                        __half2 v = __floats2half2_rn(c[mi][ni][half_*2], c[mi][ni][half_*2+1]);
                        *reinterpret_cast<__half2*>(OUT + base + ni * 8 + tg * 2) = v;
                    }
                } else {
#pragma unroll
                    for (int ni = 0; ni < 4; ni++) {
                        int dk0 = ni * 8 + tg * 2;
                        float o1x, o1y, o2x, o2y;
#pragma unroll
                        for (int j = 0; j < 2; j++) {
                            int dk = dk0 + j;
                            float x1 = c[mi][ni][half_*2 + j];
                            float x2 = c[mi][ni+4][half_*2 + j];
                            float cs = g_cos[s * 32 + dk];
                            float sn = g_sin[s * 32 + dk];
                            float v1 = x1 * cs - x2 * sn;
                            float v2 = x2 * cs + x1 * sn;
                            if (j == 0) { o1x = v1; o2x = v2; }
                            else        { o1y = v1; o2y = v2; }
                        }
                        *reinterpret_cast<__half2*>(OUT + base + dk0)      = __floats2half2_rn(o1x, o1y);
                        *reinterpret_cast<__half2*>(OUT + base + dk0 + 32) = __floats2half2_rn(o2x, o2y);
                    }
                }
            }
        }
    } else {  // MODE 3
        __half* C = (__half*)Cv0;
        const int NO = N >> 1;
#pragma unroll
        for (int mi = 0; mi < 4; mi++) {
            int r = m0 + wm * 64 + mi * 16 + g;
#pragma unroll
            for (int ni = 0; ni < 8; ni++) {
                int oc = (n0 + wn * 64 + ni * 8) / 2 + tg;
                float u1a = c[mi][ni][0], u2a = c[mi][ni][1];
                float u1b = c[mi][ni][2], u2b = c[mi][ni][3];
                C[(size_t)r * NO + oc]       = __float2half_rn(u1a * (u2a / (1.0f + expf(-u2a))));
                C[(size_t)(r + 8) * NO + oc] = __float2half_rn(u1b * (u2b / (1.0f + expf(-u2b))));
            }
        }
    }
}

// ----------------------------------------------------------------------------
// Flash attention fp16, causal. 128-row q-tiles, warp = 16 rows x ALL 64 cols.
// Register-only softmax (warp-local) + register P pass (C-frag == next A-frag).
// smem: Q 128x72 | K 2x64x72 | V 2x64x72 halves = 55296 B. One barrier per tile.
// ----------------------------------------------------------------------------
#define LDH 72
#define KTI (64*LDH)                 // 4608 halves
#define QTI2 (128*LDH)               // 9216 halves
#define FA_SMEM ((QTI2 + 4*KTI)*2)   // 55296 bytes

__global__ void __launch_bounds__(256, 2) flash_attn_tc(
    const __half* __restrict__ Q, const __half* __restrict__ Kg,
    const __half* __restrict__ Vg, __half* __restrict__ ctx)
{
    extern __shared__ char fsc[];
    __half* Qs = (__half*)fsc;
    const uint32_t qsu = smem_u32(Qs);
    const uint32_t ksu = qsu + QTI2 * 2;
    const uint32_t vsu = ksu + 2 * KTI * 2;

    const int qt = (int)gridDim.x - 1 - (int)blockIdx.x;   // heavy first
    const int bh = blockIdx.y;
    const int tid = threadIdx.x;
    const int wm = tid >> 5;                // warp id = m-block (8 warps x 16 rows)
    const int lane = tid & 31;
    const int g = lane >> 2, tg = lane & 3;
    const int r15 = lane & 15;
    const int ch16 = (lane >> 4) << 4;

    const int qbase = qt * 128;
    const int rA = wm * 16 + g;             // local row (first of pair)
    const int qgA = qbase + rA, qgB = qgA + 8;

    // Q load: 128 rows x 8 x 16B chunks = 1024; 4 per thread (plain vector loads)
    const size_t baseQ = ((size_t)bh * SEQ + (size_t)qbase) * DHEAD;
#pragma unroll
    for (int it = 0; it < 4; it++) {
        int idx = tid + it * 256;
        int r = idx >> 3, c8 = (idx & 7) * 8;
        *reinterpret_cast<uint4*>(Qs + r * LDH + c8) =
            *reinterpret_cast<const uint4*>(Q + baseQ + (size_t)r * DHEAD + c8);
    }

    const int ntile = 2 * qt + 2;

    // prefetch kv tile 0 into buffer 0
    {
        const __half* Kb = Kg + ((size_t)bh * SEQ) * DHEAD;
        const __half* Vb = Vg + ((size_t)bh * SEQ) * DHEAD;
#pragma unroll
        for (int it = 0; it < 2; it++) {
            int idx = tid + it * 256;
            int r = idx >> 3, c8 = (idx & 7) * 8;
            cp16(ksu + (r * LDH + c8) * 2, Kb + (size_t)r * DHEAD + c8);
            cp16(vsu + (r * LDH + c8) * 2, Vb + (size_t)r * DHEAD + c8);
        }
        CP_COMMIT();
    }

    float co[8][4] = {};
    float rmA = -1e30f, rlA = 0.f, rmB = -1e30f, rlB = 0.f;

    for (int kt = 0; kt < ntile; kt++) {
        const int buf = kt & 1;
        CP_WAIT0();
        __syncthreads();                    // kv[buf] ready; kv[buf^1] free

        if (kt + 1 < ntile) {
            const __half* Kb = Kg + ((size_t)bh * SEQ + (size_t)(kt+1) * 64) * DHEAD;
            const __half* Vb = Vg + ((size_t)bh * SEQ + (size_t)(kt+1) * 64) * DHEAD;
            uint32_t kd = ksu + ((buf ^ 1) * KTI) * 2;
            uint32_t vd = vsu + ((buf ^ 1) * KTI) * 2;
#pragma unroll
            for (int it = 0; it < 2; it++) {
                int idx = tid + it * 256;
                int r = idx >> 3, c8 = (idx & 7) * 8;
                cp16(kd + (r * LDH + c8) * 2, Kb + (size_t)r * DHEAD + c8);
                cp16(vd + (r * LDH + c8) * 2, Vb + (size_t)r * DHEAD + c8);
            }
            CP_COMMIT();
        }

        const int kb = kt * 64;
        if (kb > qbase + wm * 16 + 15) continue;   // fully masked for this warp

        // ---- S = Q @ K^T : warp covers 16 rows x 64 cols ----
        float cs_[8][4] = {};
        {
            const uint32_t aQ = qsu + ((wm * 16 + r15) * LDH) * 2 + ch16;
            const uint32_t bK = ksu + (buf * KTI) * 2 + (r15 * LDH) * 2 + ch16;
#pragma unroll
            for (int ks = 0; ks < 4; ks++) {
                uint32_t qa[4];
                ldsm4(qa, aQ + ks * 32);
#pragma unroll
                for (int nc = 0; nc < 4; nc++) {
                    uint32_t kf[4];
                    ldsm4(kf, bK + nc * 16 * LDH * 2 + ks * 32);
                    mma_f16(cs_[nc*2],   qa, kf[0], kf[2]);
                    mma_f16(cs_[nc*2+1], qa, kf[1], kf[3]);
                }
            }
        }

        // ---- scale + causal mask ----
#pragma unroll
        for (int ni = 0; ni < 8; ni++)
#pragma unroll
            for (int jj = 0; jj < 4; jj++) cs_[ni][jj] *= 0.125f;
        if (kb + 63 > qbase + wm * 16) {
#pragma unroll
            for (int ni = 0; ni < 8; ni++) {
                int kg = kb + ni * 8 + 2 * tg;
                if (kg     > qgA) cs_[ni][0] = -1e30f;
                if (kg + 1 > qgA) cs_[ni][1] = -1e30f;
                if (kg     > qgB) cs_[ni][2] = -1e30f;
                if (kg + 1 > qgB) cs_[ni][3] = -1e30f;
            }
        }

        // ---- warp-local online softmax (registers only) ----
        {
            float mA = -1e30f, mB = -1e30f;
#pragma unroll
            for (int ni = 0; ni < 8; ni++) {
                mA = fmaxf(mA, fmaxf(cs_[ni][0], cs_[ni][1]));
                mB = fmaxf(mB, fmaxf(cs_[ni][2], cs_[ni][3]));
            }
            mA = fmaxf(mA, __shfl_xor_sync(0xffffffffu, mA, 1));
            mA = fmaxf(mA, __shfl_xor_sync(0xffffffffu, mA, 2));
            mB = fmaxf(mB, __shfl_xor_sync(0xffffffffu, mB, 1));
            mB = fmaxf(mB, __shfl_xor_sync(0xffffffffu, mB, 2));
            float mnA = fmaxf(rmA, mA), mnB = fmaxf(rmB, mB);
            float scA = __expf(rmA - mnA), scB = __expf(rmB - mnB);
            float lA = 0.f, lB = 0.f;
#pragma unroll
            for (int ni = 0; ni < 8; ni++) {
                cs_[ni][0] = __expf(cs_[ni][0] - mnA);
                cs_[ni][1] = __expf(cs_[ni][1] - mnA);
                cs_[ni][2] = __expf(cs_[ni][2] - mnB);
                cs_[ni][3] = __expf(cs_[ni][3] - mnB);
                lA += cs_[ni][0] + cs_[ni][1];
                lB += cs_[ni][2] + cs_[ni][3];
            }
            lA += __shfl_xor_sync(0xffffffffu, lA, 1);
            lA += __shfl_xor_sync(0xffffffffu, lA, 2);
            lB += __shfl_xor_sync(0xffffffffu, lB, 1);
            lB += __shfl_xor_sync(0xffffffffu, lB, 2);
            rlA = rlA * scA + lA; rmA = mnA;
            rlB = rlB * scB + lB; rmB = mnB;
#pragma unroll
            for (int ni = 0; ni < 8; ni++) {
                co[ni][0] *= scA; co[ni][1] *= scA;
                co[ni][2] *= scB; co[ni][3] *= scB;
            }
        }

        // ---- O += P @ V : P re-packed from registers (C-frag == A-frag) ----
        {
            const uint32_t vB = vsu + (buf * KTI) * 2 + ch16;
#pragma unroll
            for (int ks = 0; ks < 4; ks++) {
                uint32_t pa[4];
                pa[0] = packh2(cs_[2*ks][0],   cs_[2*ks][1]);
                pa[1] = packh2(cs_[2*ks][2],   cs_[2*ks][3]);
                pa[2] = packh2(cs_[2*ks+1][0], cs_[2*ks+1][1]);
                pa[3] = packh2(cs_[2*ks+1][2], cs_[2*ks+1][3]);
                uint32_t vrow = vB + ((ks * 16 + r15) * LDH) * 2;
#pragma unroll
                for (int nc = 0; nc < 4; nc++) {
                    uint32_t vf[4];
                    ldsm4t(vf, vrow + nc * 32);
                    mma_f16(co[nc*2],   pa, vf[0], vf[1]);
                    mma_f16(co[nc*2+1], pa, vf[2], vf[3]);
                }
            }
        }
    }

    // ---- final write (half) ----
    {
        int b = bh >> 4, h = bh & 15;
        float ilA = 1.0f / rlA, ilB = 1.0f / rlB;
#pragma unroll
        for (int half_ = 0; half_ < 2; half_++) {
            int row = qbase + wm * 16 + g + half_ * 8;
            float il = half_ ? ilB : ilA;
            size_t grow = ((size_t)b * SEQ + row) * DMODEL + h * 64;
#pragma unroll
            for (int ni = 0; ni < 8; ni++) {
                int d0 = ni * 8 + tg * 2;
                *reinterpret_cast<__half2*>(ctx + grow + d0) =
                    __floats2half2_rn(co[ni][half_*2] * il, co[ni][half_*2+1] * il);
            }
        }
    }
}

// ----------------------------------------------------------------------------
// Launch
// ----------------------------------------------------------------------------
extern "C" void kernel_launch(void* const* d_in, const int* in_sizes, int n_in,
                              void* d_out, int out_size) {
    const float* x  = (const float*)d_in[0];
    const float* wq = (const float*)d_in[2];
    const float* wk = (const float*)d_in[3];
    const float* wv = (const float*)d_in[4];
    const float* wo = (const float*)d_in[5];
    const float* w1 = (const float*)d_in[6];
    const float* w2 = (const float*)d_in[7];
    const float* g1 = (const float*)d_in[8];
    const float* g2 = (const float*)d_in[9];
    float* out = (float*)d_out;

    static __half *p_h=nullptr,*p_q=nullptr,*p_k=nullptr,*p_v=nullptr,
                  *p_ctx=nullptr,*p_ffn=nullptr,
                  *p_wqh=nullptr,*p_wkh=nullptr,*p_wvh=nullptr,*p_woh=nullptr,
                  *p_w1h=nullptr,*p_w2h=nullptr;
    static float *p_x2=nullptr;
    if (!p_h) {
        cudaGetSymbolAddress((void**)&p_h,   g_h);
        cudaGetSymbolAddress((void**)&p_q,   g_q);
        cudaGetSymbolAddress((void**)&p_k,   g_k);
        cudaGetSymbolAddress((void**)&p_v,   g_v);
        cudaGetSymbolAddress((void**)&p_ctx, g_ctx);
        cudaGetSymbolAddress((void**)&p_x2,  g_x2);
        cudaGetSymbolAddress((void**)&p_ffn, g_ffn);
        cudaGetSymbolAddress((void**)&p_wqh, g_wqh);
        cudaGetSymbolAddress((void**)&p_wkh, g_wkh);
        cudaGetSymbolAddress((void**)&p_wvh, g_wvh);
        cudaGetSymbolAddress((void**)&p_woh, g_woh);
        cudaGetSymbolAddress((void**)&p_w1h, g_w1h);
        cudaGetSymbolAddress((void**)&p_w2h, g_w2h);
        cudaFuncSetAttribute(gemm_mma<0>, cudaFuncAttributeMaxDynamicSharedMemorySize, GEMM_SMEM);
        cudaFuncSetAttribute(gemm_mma<3>, cudaFuncAttributeMaxDynamicSharedMemorySize, GEMM_SMEM);
        cudaFuncSetAttribute(gemm_mma<4>, cudaFuncAttributeMaxDynamicSharedMemorySize, GEMM_SMEM);
        cudaFuncSetAttribute(flash_attn_tc, cudaFuncAttributeMaxDynamicSharedMemorySize, FA_SMEM);
    }

    build_rope_table<<<(SEQ * 32 + 255) / 256, 256>>>();

    // one-shot weight conversion (w1 permuted inside)
    cvt_all<<<(CVT_TOTAL + 255) / 256, 256>>>(
        (const float2*)wq, (const float2*)wk, (const float2*)wv, (const float2*)wo,
        (const float2*)w1, (const float2*)w2,
        (__half2*)p_wqh, (__half2*)p_wkh, (__half2*)p_wvh, (__half2*)p_woh,
        (__half2*)p_w1h, (__half2*)p_w2h);

    // --- attention sublayer ---
    rmsnorm_k<<<ROWS, 256>>>(x, g1, p_h);

    dim3 gqkv(3 * DMODEL / 256, ROWS / 128);   // (12, 32)
    gemm_mma<4><<<gqkv, 256, GEMM_SMEM>>>(p_h, p_wqh, p_wkh, p_wvh, nullptr,
                                          p_q, p_k, p_v, ROWS, 3 * DMODEL, DMODEL);

    flash_attn_tc<<<dim3(SEQ / 128, BATCH * NHEAD), 256, FA_SMEM>>>(p_q, p_k, p_v, p_ctx);

    dim3 gproj(DMODEL / 256, ROWS / 128);      // (4, 32)
    gemm_mma<0><<<gproj, 256, GEMM_SMEM>>>(p_ctx, p_woh, nullptr, nullptr, x,
                                           p_x2, nullptr, nullptr, ROWS, DMODEL, DMODEL);

    // --- FFN sublayer ---
    rmsnorm_k<<<ROWS, 256>>>(p_x2, g2, p_h);
    dim3 gup(2 * DFF / 256, ROWS / 128);       // (32, 32)
    gemm_mma<3><<<gup, 256, GEMM_SMEM>>>(p_h, p_w1h, nullptr, nullptr, nullptr,
                                         p_ffn, nullptr, nullptr, ROWS, 2 * DFF, DMODEL);
    dim3 gdown(DMODEL / 256, ROWS / 128);      // (4, 32)
    gemm_mma<0><<<gdown, 256, GEMM_SMEM>>>(p_ffn, p_w2h, nullptr, nullptr, p_x2,
                                           out, nullptr, nullptr, ROWS, DMODEL, DFF);
}

// round 16
// speedup vs baseline: 1.0510x; 1.0024x over previous
#include <cuda_runtime.h>
#include <cuda_fp16.h>
#include <math.h>
#include <stdint.h>

// Problem constants
#define BATCH 2
#define SEQ   2048
#define DMODEL 1024
#define NHEAD 16
#define DHEAD 64
#define DFF   4096
#define ROWS  (BATCH*SEQ)   // 4096

// ----------------------------------------------------------------------------
// Scratch (device globals; no allocations allowed)
// ----------------------------------------------------------------------------
__device__ __half g_h   [(size_t)ROWS*DMODEL];
__device__ __half g_q   [(size_t)ROWS*DMODEL];
__device__ __half g_k   [(size_t)ROWS*DMODEL];
__device__ __half g_v   [(size_t)ROWS*DMODEL];
__device__ __half g_ctx [(size_t)ROWS*DMODEL];
__device__ float  g_x2  [(size_t)ROWS*DMODEL];
__device__ __half g_ffn [(size_t)ROWS*DFF];
__device__ float  g_cos [SEQ*32];
__device__ float  g_sin [SEQ*32];
// fp16 weights
__device__ __half g_wqh [(size_t)DMODEL*DMODEL];
__device__ __half g_wkh [(size_t)DMODEL*DMODEL];
__device__ __half g_wvh [(size_t)DMODEL*DMODEL];
__device__ __half g_woh [(size_t)DMODEL*DMODEL];
__device__ __half g_w1h [(size_t)2*DFF*DMODEL];   // row-permuted u1/u2 interleaved
__device__ __half g_w2h [(size_t)DMODEL*DFF];

// ----------------------------------------------------------------------------
// Helpers
// ----------------------------------------------------------------------------
__device__ __forceinline__ uint32_t smem_u32(const void* p) {
    uint32_t a;
    asm("{ .reg .u64 t; cvta.to.shared.u64 t, %1; cvt.u32.u64 %0, t; }" : "=r"(a) : "l"(p));
    return a;
}
__device__ __forceinline__ void cp16(uint32_t dst, const void* src) {
    asm volatile("cp.async.ca.shared.global [%0], [%1], 16;" :: "r"(dst), "l"(src) : "memory");
}
#define CP_COMMIT() asm volatile("cp.async.commit_group;" ::: "memory")
#define CP_WAIT1()  asm volatile("cp.async.wait_group 1;" ::: "memory")
#define CP_WAIT0()  asm volatile("cp.async.wait_group 0;" ::: "memory")

// fp16 mma, fp32 accumulate: m16n8k16
__device__ __forceinline__ void mma_f16(float* c, const uint32_t* a, uint32_t b0, uint32_t b1) {
    asm volatile("mma.sync.aligned.m16n8k16.row.col.f32.f16.f16.f32 "
                 "{%0,%1,%2,%3}, {%4,%5,%6,%7}, {%8,%9}, {%0,%1,%2,%3};"
                 : "+f"(c[0]), "+f"(c[1]), "+f"(c[2]), "+f"(c[3])
                 : "r"(a[0]), "r"(a[1]), "r"(a[2]), "r"(a[3]), "r"(b0), "r"(b1));
}
__device__ __forceinline__ void ldsm4(uint32_t* r, uint32_t addr) {
    asm volatile("ldmatrix.sync.aligned.m8n8.x4.shared.b16 {%0,%1,%2,%3}, [%4];"
                 : "=r"(r[0]), "=r"(r[1]), "=r"(r[2]), "=r"(r[3]) : "r"(addr));
}
__device__ __forceinline__ void ldsm4t(uint32_t* r, uint32_t addr) {
    asm volatile("ldmatrix.sync.aligned.m8n8.x4.trans.shared.b16 {%0,%1,%2,%3}, [%4];"
                 : "=r"(r[0]), "=r"(r[1]), "=r"(r[2]), "=r"(r[3]) : "r"(addr));
}
__device__ __forceinline__ uint32_t packh2(float a, float b) {
    __half2 h = __floats2half2_rn(a, b);
    return *reinterpret_cast<uint32_t*>(&h);
}

// ----------------------------------------------------------------------------
// RoPE table
// ----------------------------------------------------------------------------
__global__ void build_rope_table() {
    int idx = blockIdx.x * blockDim.x + threadIdx.x;
    if (idx >= SEQ * 32) return;
    int s = idx / 32, j = idx % 32;
    double invf = exp(-(double)j * (9.210340371976184 / 32.0));
    double a = (double)s * invf;
    g_cos[idx] = (float)cos(a);
    g_sin[idx] = (float)sin(a);
}

// ----------------------------------------------------------------------------
// One-shot weight conversion fp32->fp16 (w1 permuted at the same time)
// ----------------------------------------------------------------------------
#define NW2  (DMODEL*DMODEL/2)       // 524288 half2 per square weight
#define W1_2 (2*DFF*DMODEL/2)        // 4194304
#define W2_2 (DMODEL*DFF/2)          // 2097152
#define CVT_TOTAL (4*NW2 + W1_2 + W2_2)

__global__ __launch_bounds__(256) void cvt_all(
    const float2* __restrict__ wq, const float2* __restrict__ wk,
    const float2* __restrict__ wv, const float2* __restrict__ wo,
    const float2* __restrict__ w1, const float2* __restrict__ w2,
    __half2* __restrict__ oq, __half2* __restrict__ ok,
    __half2* __restrict__ ov, __half2* __restrict__ oo,
    __half2* __restrict__ o1, __half2* __restrict__ o2)
{
    int i = blockIdx.x * 256 + threadIdx.x;
    if (i < 4 * NW2) {
        int w = i / NW2, j = i - w * NW2;
        const float2* src = (w == 0) ? wq : (w == 1) ? wk : (w == 2) ? wv : wo;
        __half2* dst = (w == 0) ? oq : (w == 1) ? ok : (w == 2) ? ov : oo;
        dst[j] = __float22half2_rn(src[j]);
    } else if (i < 4 * NW2 + W1_2) {
        int j = i - 4 * NW2;
        const int C2 = DMODEL / 2;
        int row = j / C2, c = j - row * C2;
        int src = (row & 1) ? (DFF + (row >> 1)) : (row >> 1);
        o1[j] = __float22half2_rn(w1[(size_t)src * C2 + c]);
    } else if (i < CVT_TOTAL) {
        int j = i - 4 * NW2 - W1_2;
        o2[j] = __float22half2_rn(w2[j]);
    }
}

// ----------------------------------------------------------------------------
// RMSNorm -> half output
// ----------------------------------------------------------------------------
__global__ __launch_bounds__(256) void rmsnorm_k(const float* __restrict__ x,
                                                 const float* __restrict__ g,
                                                 __half* __restrict__ o) {
    int row = blockIdx.x;
    const float* xr = x + (size_t)row * DMODEL;
    float ss = 0.f;
    for (int c = threadIdx.x; c < DMODEL; c += 256) { float v = xr[c]; ss += v * v; }
    __shared__ float sm[8];
    for (int off = 16; off; off >>= 1) ss += __shfl_down_sync(0xffffffffu, ss, off);
    if ((threadIdx.x & 31) == 0) sm[threadIdx.x >> 5] = ss;
    __syncthreads();
    if (threadIdx.x < 8) {
        float v = sm[threadIdx.x];
        for (int off = 4; off; off >>= 1) v += __shfl_down_sync(0xffu, v, off);
        if (threadIdx.x == 0) sm[0] = v;
    }
    __syncthreads();
    float inv = 1.0f / sqrtf(sm[0] / (float)DMODEL + 1e-6f);
    __half* orow = o + (size_t)row * DMODEL;
    for (int c = threadIdx.x; c < DMODEL; c += 256)
        orow[c] = __float2half_rn(xr[c] * inv * g[c]);
}

// ----------------------------------------------------------------------------
// FP16 mma.sync GEMM. BM=128 BN=256 BK=32(halves), 3-stage cp.async.
// 256 threads = 8 warps, warp grid 2m x 4n, warp tile 64x64.
// MODE 0: fp32 store (+res). MODE 3: SwiGLU half out. MODE 4: fused QKV half out.
// ----------------------------------------------------------------------------
#define BK 32
#define LDTH 40                          // halves per row (80 bytes)
#define STG_A (128*LDTH)                 // halves
#define STG_B (256*LDTH)
#define STG_T (STG_A+STG_B)              // 15360 halves
#define GSTAGES 3
#define GEMM_SMEM (GSTAGES*STG_T*2)      // 92160 bytes

template<int MODE>
__global__ void __launch_bounds__(256, 1) gemm_mma(
    const __half* __restrict__ A, const __half* __restrict__ B,
    const __half* __restrict__ B2, const __half* __restrict__ B3,
    const float* __restrict__ res, void* __restrict__ Cv0,
    void* __restrict__ Cv1, void* __restrict__ Cv2,
    int M, int N, int K)
{
    extern __shared__ char smc[];
    const uint32_t ssu = smem_u32(smc);

    const int tid = threadIdx.x;
    const int wid = tid >> 5, lane = tid & 31;
    const int wm = wid & 1, wn = wid >> 1;
    const int g = lane >> 2, tg = lane & 3;
    const int m0 = blockIdx.y * 128, n0 = blockIdx.x * 256;

    const int arow = tid >> 1, achk = (tid & 1) * 2;
    const __half* APtr[2];
#pragma unroll
    for (int it = 0; it < 2; it++)
        APtr[it] = A + (size_t)(m0 + arow) * K + (achk + it) * 8;

    const int brow = tid >> 1, bchk = (tid & 1) * 2;
    const __half* BPtr[4];
    {
        const __half* W = B;
        int nbase = n0;
        if (MODE == 4) {
            int region = n0 >> 10; nbase = n0 & 1023;
            W = (region == 0) ? B : (region == 1) ? B2 : B3;
        }
#pragma unroll
        for (int rt = 0; rt < 2; rt++)
#pragma unroll
            for (int jt = 0; jt < 2; jt++)
                BPtr[rt * 2 + jt] = W + (size_t)(nbase + brow + rt * 128) * K
                                      + (bchk + jt) * 8;
    }

    const uint32_t stAoff = ssu + (arow * LDTH + achk * 8) * 2;
    const uint32_t stBoff = ssu + STG_A * 2 + (brow * LDTH + bchk * 8) * 2;

    const int niter = K >> 5;

#pragma unroll
    for (int s = 0; s < 2; s++) {
        uint32_t off = s * STG_T * 2;
        int ko = s * BK;
#pragma unroll
        for (int it = 0; it < 2; it++)
            cp16(stAoff + off + it * 16, APtr[it] + ko);
#pragma unroll
        for (int rt = 0; rt < 2; rt++)
#pragma unroll
            for (int jt = 0; jt < 2; jt++)
                cp16(stBoff + off + rt * 128 * LDTH * 2 + jt * 16,
                     BPtr[rt * 2 + jt] + ko);
        CP_COMMIT();
    }

    float c[4][8][4] = {};

    const int r15 = lane & 15;
    const int ch16 = (lane >> 4) << 4;
    const uint32_t aAddr0 = (uint32_t)((wm * 64 + r15) * LDTH * 2 + ch16);
    const uint32_t bAddr0 = (uint32_t)(STG_A * 2 + (wn * 64 + r15) * LDTH * 2 + ch16);

    int bufc = 0;
    for (int i = 0; i < niter; i++) {
        CP_WAIT1();
        __syncthreads();

        int nb = i + 2;
        if (nb < niter) {
            int bufn = bufc + 2; if (bufn >= 3) bufn -= 3;
            uint32_t off = bufn * STG_T * 2;
            int ko = nb * BK;
#pragma unroll
            for (int it = 0; it < 2; it++)
                cp16(stAoff + off + it * 16, APtr[it] + ko);
#pragma unroll
            for (int rt = 0; rt < 2; rt++)
#pragma unroll
                for (int jt = 0; jt < 2; jt++)
                    cp16(stBoff + off + rt * 128 * LDTH * 2 + jt * 16,
                         BPtr[rt * 2 + jt] + ko);
        }
        CP_COMMIT();

        const uint32_t stA = ssu + bufc * STG_T * 2 + aAddr0;
        const uint32_t stB = ssu + bufc * STG_T * 2 + bAddr0;
#pragma unroll
        for (int ks = 0; ks < 2; ks++) {
            uint32_t af[4][4], bf[4][4];
#pragma unroll
            for (int mi = 0; mi < 4; mi++)
                ldsm4(af[mi], stA + mi * 16 * LDTH * 2 + ks * 32);
#pragma unroll
            for (int grp = 0; grp < 4; grp++)
                ldsm4(bf[grp], stB + grp * 16 * LDTH * 2 + ks * 32);
#pragma unroll
            for (int mi = 0; mi < 4; mi++)
#pragma unroll
                for (int ni = 0; ni < 8; ni++) {
                    int grp = ni >> 1, odd = ni & 1;
                    mma_f16(c[mi][ni], af[mi], bf[grp][odd], bf[grp][2 + odd]);
                }
        }
        if (++bufc == 3) bufc = 0;
    }

    if (MODE == 0) {
        float* C = (float*)Cv0;
#pragma unroll
        for (int mi = 0; mi < 4; mi++) {
            int r = m0 + wm * 64 + mi * 16 + g;
#pragma unroll
            for (int ni = 0; ni < 8; ni++) {
                int cc = n0 + wn * 64 + ni * 8 + tg * 2;
                size_t o1 = (size_t)r * N + cc;
                size_t o2 = (size_t)(r + 8) * N + cc;
                float2 v1 = make_float2(c[mi][ni][0], c[mi][ni][1]);
                float2 v2 = make_float2(c[mi][ni][2], c[mi][ni][3]);
                if (res) {
                    float2 r1 = *reinterpret_cast<const float2*>(res + o1);
                    float2 r2 = *reinterpret_cast<const float2*>(res + o2);
                    v1.x += r1.x; v1.y += r1.y; v2.x += r2.x; v2.y += r2.y;
                }
                *reinterpret_cast<float2*>(C + o1) = v1;
                *reinterpret_cast<float2*>(C + o2) = v2;
            }
        }
    } else if (MODE == 4) {
        int region = n0 >> 10, nloc = n0 & 1023;
        __half* OUT = (region == 0) ? (__half*)Cv0 : (region == 1) ? (__half*)Cv1 : (__half*)Cv2;
        int h = (nloc + wn * 64) >> 6;
        bool doRope = (region < 2);
#pragma unroll
        for (int mi = 0; mi < 4; mi++) {
#pragma unroll
            for (int half_ = 0; half_ < 2; half_++) {
                int r = m0 + wm * 64 + mi * 16 + g + half_ * 8;
                int bb = r >> 11, s = r & 2047;
                size_t base = (((size_t)(bb * NHEAD + h)) * SEQ + s) * 64;
                if (!doRope) {
#pragma unroll
                    for (int ni = 0; ni < 8; ni++) {
                        __half2 v = __floats2half2_rn(c[mi][ni][half_*2], c[mi][ni][half_*2+1]);
                        *reinterpret_cast<__half2*>(OUT + base + ni * 8 + tg * 2) = v;
                    }
                } else {
#pragma unroll
                    for (int ni = 0; ni < 4; ni++) {
                        int dk0 = ni * 8 + tg * 2;
                        float o1x, o1y, o2x, o2y;
#pragma unroll
                        for (int j = 0; j < 2; j++) {
                            int dk = dk0 + j;
                            float x1 = c[mi][ni][half_*2 + j];
                            float x2 = c[mi][ni+4][half_*2 + j];
                            float cs = g_cos[s * 32 + dk];
                            float sn = g_sin[s * 32 + dk];
                            float v1 = x1 * cs - x2 * sn;
                            float v2 = x2 * cs + x1 * sn;
                            if (j == 0) { o1x = v1; o2x = v2; }
                            else        { o1y = v1; o2y = v2; }
                        }
                        *reinterpret_cast<__half2*>(OUT + base + dk0)      = __floats2half2_rn(o1x, o1y);
                        *reinterpret_cast<__half2*>(OUT + base + dk0 + 32) = __floats2half2_rn(o2x, o2y);
                    }
                }
            }
        }
    } else {  // MODE 3
        __half* C = (__half*)Cv0;
        const int NO = N >> 1;
#pragma unroll
        for (int mi = 0; mi < 4; mi++) {
            int r = m0 + wm * 64 + mi * 16 + g;
#pragma unroll
            for (int ni = 0; ni < 8; ni++) {
                int oc = (n0 + wn * 64 + ni * 8) / 2 + tg;
                float u1a = c[mi][ni][0], u2a = c[mi][ni][1];
                float u1b = c[mi][ni][2], u2b = c[mi][ni][3];
                C[(size_t)r * NO + oc]       = __float2half_rn(u1a * (u2a / (1.0f + expf(-u2a))));
                C[(size_t)(r + 8) * NO + oc] = __float2half_rn(u1b * (u2b / (1.0f + expf(-u2b))));
            }
        }
    }
}

// ----------------------------------------------------------------------------
// Flash attention fp16, causal. 128-row q-tiles, warp = 16 rows x ALL 64 cols.
// Register-only softmax (warp-local) + register P pass (C-frag == next A-frag).
// smem: Q 128x72 | K 2x64x72 | V 2x64x72 halves = 55296 B. One barrier per tile.
// ----------------------------------------------------------------------------
#define LDH 72
#define KTI (64*LDH)                 // 4608 halves
#define QTI2 (128*LDH)               // 9216 halves
#define FA_SMEM ((QTI2 + 4*KTI)*2)   // 55296 bytes

__global__ void __launch_bounds__(256, 2) flash_attn_tc(
    const __half* __restrict__ Q, const __half* __restrict__ Kg,
    const __half* __restrict__ Vg, __half* __restrict__ ctx)
{
    extern __shared__ char fsc[];
    __half* Qs = (__half*)fsc;
    const uint32_t qsu = smem_u32(Qs);
    const uint32_t ksu = qsu + QTI2 * 2;
    const uint32_t vsu = ksu + 2 * KTI * 2;

    const int qt = (int)gridDim.x - 1 - (int)blockIdx.x;   // heavy first
    const int bh = blockIdx.y;
    const int tid = threadIdx.x;
    const int wm = tid >> 5;                // warp id = m-block (8 warps x 16 rows)
    const int lane = tid & 31;
    const int g = lane >> 2, tg = lane & 3;
    const int r15 = lane & 15;
    const int ch16 = (lane >> 4) << 4;

    const int qbase = qt * 128;
    const int rA = wm * 16 + g;             // local row (first of pair)
    const int qgA = qbase + rA, qgB = qgA + 8;

    // Q load: 128 rows x 8 x 16B chunks = 1024; 4 per thread (plain vector loads)
    const size_t baseQ = ((size_t)bh * SEQ + (size_t)qbase) * DHEAD;
#pragma unroll
    for (int it = 0; it < 4; it++) {
        int idx = tid + it * 256;
        int r = idx >> 3, c8 = (idx & 7) * 8;
        *reinterpret_cast<uint4*>(Qs + r * LDH + c8) =
            *reinterpret_cast<const uint4*>(Q + baseQ + (size_t)r * DHEAD + c8);
    }

    const int ntile = 2 * qt + 2;

    // prefetch kv tile 0 into buffer 0
    {
        const __half* Kb = Kg + ((size_t)bh * SEQ) * DHEAD;
        const __half* Vb = Vg + ((size_t)bh * SEQ) * DHEAD;
#pragma unroll
        for (int it = 0; it < 2; it++) {
            int idx = tid + it * 256;
            int r = idx >> 3, c8 = (idx & 7) * 8;
            cp16(ksu + (r * LDH + c8) * 2, Kb + (size_t)r * DHEAD + c8);
            cp16(vsu + (r * LDH + c8) * 2, Vb + (size_t)r * DHEAD + c8);
        }
        CP_COMMIT();
    }

    float co[8][4] = {};
    float rmA = -1e30f, rlA = 0.f, rmB = -1e30f, rlB = 0.f;

    for (int kt = 0; kt < ntile; kt++) {
        const int buf = kt & 1;
        CP_WAIT0();
        __syncthreads();                    // kv[buf] ready; kv[buf^1] free

        if (kt + 1 < ntile) {
            const __half* Kb = Kg + ((size_t)bh * SEQ + (size_t)(kt+1) * 64) * DHEAD;
            const __half* Vb = Vg + ((size_t)bh * SEQ + (size_t)(kt+1) * 64) * DHEAD;
            uint32_t kd = ksu + ((buf ^ 1) * KTI) * 2;
            uint32_t vd = vsu + ((buf ^ 1) * KTI) * 2;
#pragma unroll
            for (int it = 0; it < 2; it++) {
                int idx = tid + it * 256;
                int r = idx >> 3, c8 = (idx & 7) * 8;
                cp16(kd + (r * LDH + c8) * 2, Kb + (size_t)r * DHEAD + c8);
                cp16(vd + (r * LDH + c8) * 2, Vb + (size_t)r * DHEAD + c8);
            }
            CP_COMMIT();
        }

        const int kb = kt * 64;
        if (kb > qbase + wm * 16 + 15) continue;   // fully masked for this warp

        // ---- S = Q @ K^T : warp covers 16 rows x 64 cols ----
        float cs_[8][4] = {};
        {
            const uint32_t aQ = qsu + ((wm * 16 + r15) * LDH) * 2 + ch16;
            const uint32_t bK = ksu + (buf * KTI) * 2 + (r15 * LDH) * 2 + ch16;
#pragma unroll
            for (int ks = 0; ks < 4; ks++) {
                uint32_t qa[4];
                ldsm4(qa, aQ + ks * 32);
#pragma unroll
                for (int nc = 0; nc < 4; nc++) {
                    uint32_t kf[4];
                    ldsm4(kf, bK + nc * 16 * LDH * 2 + ks * 32);
                    mma_f16(cs_[nc*2],   qa, kf[0], kf[2]);
                    mma_f16(cs_[nc*2+1], qa, kf[1], kf[3]);
                }
            }
        }

        // ---- scale + causal mask ----
#pragma unroll
        for (int ni = 0; ni < 8; ni++)
#pragma unroll
            for (int jj = 0; jj < 4; jj++) cs_[ni][jj] *= 0.125f;
        if (kb + 63 > qbase + wm * 16) {
#pragma unroll
            for (int ni = 0; ni < 8; ni++) {
                int kg = kb + ni * 8 + 2 * tg;
                if (kg     > qgA) cs_[ni][0] = -1e30f;
                if (kg + 1 > qgA) cs_[ni][1] = -1e30f;
                if (kg     > qgB) cs_[ni][2] = -1e30f;
                if (kg + 1 > qgB) cs_[ni][3] = -1e30f;
            }
        }

        // ---- warp-local online softmax (registers only) ----
        {
            float mA = -1e30f, mB = -1e30f;
#pragma unroll
            for (int ni = 0; ni < 8; ni++) {
                mA = fmaxf(mA, fmaxf(cs_[ni][0], cs_[ni][1]));
                mB = fmaxf(mB, fmaxf(cs_[ni][2], cs_[ni][3]));
            }
            mA = fmaxf(mA, __shfl_xor_sync(0xffffffffu, mA, 1));
            mA = fmaxf(mA, __shfl_xor_sync(0xffffffffu, mA, 2));
            mB = fmaxf(mB, __shfl_xor_sync(0xffffffffu, mB, 1));
            mB = fmaxf(mB, __shfl_xor_sync(0xffffffffu, mB, 2));
            float mnA = fmaxf(rmA, mA), mnB = fmaxf(rmB, mB);
            float scA = __expf(rmA - mnA), scB = __expf(rmB - mnB);
            float lA = 0.f, lB = 0.f;
#pragma unroll
            for (int ni = 0; ni < 8; ni++) {
                cs_[ni][0] = __expf(cs_[ni][0] - mnA);
                cs_[ni][1] = __expf(cs_[ni][1] - mnA);
                cs_[ni][2] = __expf(cs_[ni][2] - mnB);
                cs_[ni][3] = __expf(cs_[ni][3] - mnB);
                lA += cs_[ni][0] + cs_[ni][1];
                lB += cs_[ni][2] + cs_[ni][3];
            }
            lA += __shfl_xor_sync(0xffffffffu, lA, 1);
            lA += __shfl_xor_sync(0xffffffffu, lA, 2);
            lB += __shfl_xor_sync(0xffffffffu, lB, 1);
            lB += __shfl_xor_sync(0xffffffffu, lB, 2);
            rlA = rlA * scA + lA; rmA = mnA;
            rlB = rlB * scB + lB; rmB = mnB;
#pragma unroll
            for (int ni = 0; ni < 8; ni++) {
                co[ni][0] *= scA; co[ni][1] *= scA;
                co[ni][2] *= scB; co[ni][3] *= scB;
            }
        }

        // ---- O += P @ V : P re-packed from registers (C-frag == A-frag) ----
        {
            const uint32_t vB = vsu + (buf * KTI) * 2 + ch16;
#pragma unroll
            for (int ks = 0; ks < 4; ks++) {
                uint32_t pa[4];
                pa[0] = packh2(cs_[2*ks][0],   cs_[2*ks][1]);
                pa[1] = packh2(cs_[2*ks][2],   cs_[2*ks][3]);
                pa[2] = packh2(cs_[2*ks+1][0], cs_[2*ks+1][1]);
                pa[3] = packh2(cs_[2*ks+1][2], cs_[2*ks+1][3]);
                uint32_t vrow = vB + ((ks * 16 + r15) * LDH) * 2;
#pragma unroll
                for (int nc = 0; nc < 4; nc++) {
                    uint32_t vf[4];
                    ldsm4t(vf, vrow + nc * 32);
                    mma_f16(co[nc*2],   pa, vf[0], vf[1]);
                    mma_f16(co[nc*2+1], pa, vf[2], vf[3]);
                }
            }
        }
    }

    // ---- final write (half) ----
    {
        int b = bh >> 4, h = bh & 15;
        float ilA = 1.0f / rlA, ilB = 1.0f / rlB;
#pragma unroll
        for (int half_ = 0; half_ < 2; half_++) {
            int row = qbase + wm * 16 + g + half_ * 8;
            float il = half_ ? ilB : ilA;
            size_t grow = ((size_t)b * SEQ + row) * DMODEL + h * 64;
#pragma unroll
            for (int ni = 0; ni < 8; ni++) {
                int d0 = ni * 8 + tg * 2;
                *reinterpret_cast<__half2*>(ctx + grow + d0) =
                    __floats2half2_rn(co[ni][half_*2] * il, co[ni][half_*2+1] * il);
            }
        }
    }
}

// ----------------------------------------------------------------------------
// Launch
// ----------------------------------------------------------------------------
extern "C" void kernel_launch(void* const* d_in, const int* in_sizes, int n_in,
                              void* d_out, int out_size) {
    const float* x  = (const float*)d_in[0];
    const float* wq = (const float*)d_in[2];
    const float* wk = (const float*)d_in[3];
    const float* wv = (const float*)d_in[4];
    const float* wo = (const float*)d_in[5];
    const float* w1 = (const float*)d_in[6];
    const float* w2 = (const float*)d_in[7];
    const float* g1 = (const float*)d_in[8];
    const float* g2 = (const float*)d_in[9];
    float* out = (float*)d_out;

    static __half *p_h=nullptr,*p_q=nullptr,*p_k=nullptr,*p_v=nullptr,
                  *p_ctx=nullptr,*p_ffn=nullptr,
                  *p_wqh=nullptr,*p_wkh=nullptr,*p_wvh=nullptr,*p_woh=nullptr,
                  *p_w1h=nullptr,*p_w2h=nullptr;
    static float *p_x2=nullptr;
    if (!p_h) {
        cudaGetSymbolAddress((void**)&p_h,   g_h);
        cudaGetSymbolAddress((void**)&p_q,   g_q);
        cudaGetSymbolAddress((void**)&p_k,   g_k);
        cudaGetSymbolAddress((void**)&p_v,   g_v);
        cudaGetSymbolAddress((void**)&p_ctx, g_ctx);
        cudaGetSymbolAddress((void**)&p_x2,  g_x2);
        cudaGetSymbolAddress((void**)&p_ffn, g_ffn);
        cudaGetSymbolAddress((void**)&p_wqh, g_wqh);
        cudaGetSymbolAddress((void**)&p_wkh, g_wkh);
        cudaGetSymbolAddress((void**)&p_wvh, g_wvh);
        cudaGetSymbolAddress((void**)&p_woh, g_woh);
        cudaGetSymbolAddress((void**)&p_w1h, g_w1h);
        cudaGetSymbolAddress((void**)&p_w2h, g_w2h);
        cudaFuncSetAttribute(gemm_mma<0>, cudaFuncAttributeMaxDynamicSharedMemorySize, GEMM_SMEM);
        cudaFuncSetAttribute(gemm_mma<3>, cudaFuncAttributeMaxDynamicSharedMemorySize, GEMM_SMEM);
        cudaFuncSetAttribute(gemm_mma<4>, cudaFuncAttributeMaxDynamicSharedMemorySize, GEMM_SMEM);
        cudaFuncSetAttribute(flash_attn_tc, cudaFuncAttributeMaxDynamicSharedMemorySize, FA_SMEM);
    }

    build_rope_table<<<(SEQ * 32 + 255) / 256, 256>>>();

    // one-shot weight conversion (w1 permuted inside)
    cvt_all<<<(CVT_TOTAL + 255) / 256, 256>>>(
        (const float2*)wq, (const float2*)wk, (const float2*)wv, (const float2*)wo,
        (const float2*)w1, (const float2*)w2,
        (__half2*)p_wqh, (__half2*)p_wkh, (__half2*)p_wvh, (__half2*)p_woh,
        (__half2*)p_w1h, (__half2*)p_w2h);

    // --- attention sublayer ---
    rmsnorm_k<<<ROWS, 256>>>(x, g1, p_h);

    dim3 gqkv(3 * DMODEL / 256, ROWS / 128);   // (12, 32)
    gemm_mma<4><<<gqkv, 256, GEMM_SMEM>>>(p_h, p_wqh, p_wkh, p_wvh, nullptr,
                                          p_q, p_k, p_v, ROWS, 3 * DMODEL, DMODEL);

    flash_attn_tc<<<dim3(SEQ / 128, BATCH * NHEAD), 256, FA_SMEM>>>(p_q, p_k, p_v, p_ctx);

    dim3 gproj(DMODEL / 256, ROWS / 128);      // (4, 32)
    gemm_mma<0><<<gproj, 256, GEMM_SMEM>>>(p_ctx, p_woh, nullptr, nullptr, x,
                                           p_x2, nullptr, nullptr, ROWS, DMODEL, DMODEL);

    // --- FFN sublayer ---
    rmsnorm_k<<<ROWS, 256>>>(p_x2, g2, p_h);
    dim3 gup(2 * DFF / 256, ROWS / 128);       // (32, 32)
    gemm_mma<3><<<gup, 256, GEMM_SMEM>>>(p_h, p_w1h, nullptr, nullptr, nullptr,
                                         p_ffn, nullptr, nullptr, ROWS, 2 * DFF, DMODEL);
    dim3 gdown(DMODEL / 256, ROWS / 128);      // (4, 32)
    gemm_mma<0><<<gdown, 256, GEMM_SMEM>>>(p_ffn, p_w2h, nullptr, nullptr, p_x2,
                                           out, nullptr, nullptr, ROWS, DMODEL, DFF);
}

// round 17
// speedup vs baseline: 1.0516x; 1.0006x over previous
#include <cuda_runtime.h>
#include <cuda_fp16.h>
#include <math.h>
#include <stdint.h>

// Problem constants
#define BATCH 2
#define SEQ   2048
#define DMODEL 1024
#define NHEAD 16
#define DHEAD 64
#define DFF   4096
#define ROWS  (BATCH*SEQ)   // 4096

// ----------------------------------------------------------------------------
// Scratch (device globals; no allocations allowed)
// ----------------------------------------------------------------------------
__device__ __half g_h   [(size_t)ROWS*DMODEL];
__device__ __half g_q   [(size_t)ROWS*DMODEL];
__device__ __half g_k   [(size_t)ROWS*DMODEL];
__device__ __half g_v   [(size_t)ROWS*DMODEL];
__device__ __half g_ctx [(size_t)ROWS*DMODEL];
__device__ float  g_x2  [(size_t)ROWS*DMODEL];
__device__ __half g_ffn [(size_t)ROWS*DFF];
__device__ float  g_cos [SEQ*32];
__device__ float  g_sin [SEQ*32];
// fp16 weights
__device__ __half g_wqh [(size_t)DMODEL*DMODEL];
__device__ __half g_wkh [(size_t)DMODEL*DMODEL];
__device__ __half g_wvh [(size_t)DMODEL*DMODEL];
__device__ __half g_woh [(size_t)DMODEL*DMODEL];
__device__ __half g_w1h [(size_t)2*DFF*DMODEL];   // row-permuted u1/u2 interleaved
__device__ __half g_w2h [(size_t)DMODEL*DFF];

// ----------------------------------------------------------------------------
// Helpers
// ----------------------------------------------------------------------------
__device__ __forceinline__ uint32_t smem_u32(const void* p) {
    uint32_t a;
    asm("{ .reg .u64 t; cvta.to.shared.u64 t, %1; cvt.u32.u64 %0, t; }" : "=r"(a) : "l"(p));
    return a;
}
__device__ __forceinline__ void cp16(uint32_t dst, const void* src) {
    asm volatile("cp.async.ca.shared.global [%0], [%1], 16;" :: "r"(dst), "l"(src) : "memory");
}
#define CP_COMMIT() asm volatile("cp.async.commit_group;" ::: "memory")
#define CP_WAIT1()  asm volatile("cp.async.wait_group 1;" ::: "memory")
#define CP_WAIT0()  asm volatile("cp.async.wait_group 0;" ::: "memory")

// fp16 mma, fp32 accumulate: m16n8k16
__device__ __forceinline__ void mma_f16(float* c, const uint32_t* a, uint32_t b0, uint32_t b1) {
    asm volatile("mma.sync.aligned.m16n8k16.row.col.f32.f16.f16.f32 "
                 "{%0,%1,%2,%3}, {%4,%5,%6,%7}, {%8,%9}, {%0,%1,%2,%3};"
                 : "+f"(c[0]), "+f"(c[1]), "+f"(c[2]), "+f"(c[3])
                 : "r"(a[0]), "r"(a[1]), "r"(a[2]), "r"(a[3]), "r"(b0), "r"(b1));
}
__device__ __forceinline__ void ldsm4(uint32_t* r, uint32_t addr) {
    asm volatile("ldmatrix.sync.aligned.m8n8.x4.shared.b16 {%0,%1,%2,%3}, [%4];"
                 : "=r"(r[0]), "=r"(r[1]), "=r"(r[2]), "=r"(r[3]) : "r"(addr));
}
__device__ __forceinline__ void ldsm4t(uint32_t* r, uint32_t addr) {
    asm volatile("ldmatrix.sync.aligned.m8n8.x4.trans.shared.b16 {%0,%1,%2,%3}, [%4];"
                 : "=r"(r[0]), "=r"(r[1]), "=r"(r[2]), "=r"(r[3]) : "r"(addr));
}
__device__ __forceinline__ uint32_t packh2(float a, float b) {
    __half2 h = __floats2half2_rn(a, b);
    return *reinterpret_cast<uint32_t*>(&h);
}

// ----------------------------------------------------------------------------
// RoPE table
// ----------------------------------------------------------------------------
__global__ void build_rope_table() {
    int idx = blockIdx.x * blockDim.x + threadIdx.x;
    if (idx >= SEQ * 32) return;
    int s = idx / 32, j = idx % 32;
    double invf = exp(-(double)j * (9.210340371976184 / 32.0));
    double a = (double)s * invf;
    g_cos[idx] = (float)cos(a);
    g_sin[idx] = (float)sin(a);
}

// ----------------------------------------------------------------------------
// One-shot weight conversion fp32->fp16 (w1 permuted at the same time)
// ----------------------------------------------------------------------------
#define NW2  (DMODEL*DMODEL/2)       // 524288 half2 per square weight
#define W1_2 (2*DFF*DMODEL/2)        // 4194304
#define W2_2 (DMODEL*DFF/2)          // 2097152
#define CVT_TOTAL (4*NW2 + W1_2 + W2_2)

__global__ __launch_bounds__(256) void cvt_all(
    const float2* __restrict__ wq, const float2* __restrict__ wk,
    const float2* __restrict__ wv, const float2* __restrict__ wo,
    const float2* __restrict__ w1, const float2* __restrict__ w2,
    __half2* __restrict__ oq, __half2* __restrict__ ok,
    __half2* __restrict__ ov, __half2* __restrict__ oo,
    __half2* __restrict__ o1, __half2* __restrict__ o2)
{
    int i = blockIdx.x * 256 + threadIdx.x;
    if (i < 4 * NW2) {
        int w = i / NW2, j = i - w * NW2;
        const float2* src = (w == 0) ? wq : (w == 1) ? wk : (w == 2) ? wv : wo;
        __half2* dst = (w == 0) ? oq : (w == 1) ? ok : (w == 2) ? ov : oo;
        dst[j] = __float22half2_rn(src[j]);
    } else if (i < 4 * NW2 + W1_2) {
        int j = i - 4 * NW2;
        const int C2 = DMODEL / 2;
        int row = j / C2, c = j - row * C2;
        int src = (row & 1) ? (DFF + (row >> 1)) : (row >> 1);
        o1[j] = __float22half2_rn(w1[(size_t)src * C2 + c]);
    } else if (i < CVT_TOTAL) {
        int j = i - 4 * NW2 - W1_2;
        o2[j] = __float22half2_rn(w2[j]);
    }
}

// ----------------------------------------------------------------------------
// RMSNorm -> half output
// ----------------------------------------------------------------------------
__global__ __launch_bounds__(256) void rmsnorm_k(const float* __restrict__ x,
                                                 const float* __restrict__ g,
                                                 __half* __restrict__ o) {
    int row = blockIdx.x;
    const float* xr = x + (size_t)row * DMODEL;
    float ss = 0.f;
    for (int c = threadIdx.x; c < DMODEL; c += 256) { float v = xr[c]; ss += v * v; }
    __shared__ float sm[8];
    for (int off = 16; off; off >>= 1) ss += __shfl_down_sync(0xffffffffu, ss, off);
    if ((threadIdx.x & 31) == 0) sm[threadIdx.x >> 5] = ss;
    __syncthreads();
    if (threadIdx.x < 8) {
        float v = sm[threadIdx.x];
        for (int off = 4; off; off >>= 1) v += __shfl_down_sync(0xffu, v, off);
        if (threadIdx.x == 0) sm[0] = v;
    }
    __syncthreads();
    float inv = 1.0f / sqrtf(sm[0] / (float)DMODEL + 1e-6f);
    __half* orow = o + (size_t)row * DMODEL;
    for (int c = threadIdx.x; c < DMODEL; c += 256)
        orow[c] = __float2half_rn(xr[c] * inv * g[c]);
}

// ----------------------------------------------------------------------------
// FP16 mma.sync GEMM. BM=128 BN=256 BK=32(halves), 3-stage cp.async.
// 256 threads = 8 warps, warp grid 2m x 4n, warp tile 64x64.
// MODE 0: fp32 store (+res). MODE 3: SwiGLU half out. MODE 4: fused QKV half out.
// ----------------------------------------------------------------------------
#define BK 32
#define LDTH 40                          // halves per row (80 bytes)
#define STG_A (128*LDTH)                 // halves
#define STG_B (256*LDTH)
#define STG_T (STG_A+STG_B)              // 15360 halves
#define GSTAGES 3
#define GEMM_SMEM (GSTAGES*STG_T*2)      // 92160 bytes

template<int MODE>
__global__ void __launch_bounds__(256, 1) gemm_mma(
    const __half* __restrict__ A, const __half* __restrict__ B,
    const __half* __restrict__ B2, const __half* __restrict__ B3,
    const float* __restrict__ res, void* __restrict__ Cv0,
    void* __restrict__ Cv1, void* __restrict__ Cv2,
    int M, int N, int K)
{
    extern __shared__ char smc[];
    const uint32_t ssu = smem_u32(smc);

    const int tid = threadIdx.x;
    const int wid = tid >> 5, lane = tid & 31;
    const int wm = wid & 1, wn = wid >> 1;
    const int g = lane >> 2, tg = lane & 3;
    const int m0 = blockIdx.y * 128, n0 = blockIdx.x * 256;

    const int arow = tid >> 1, achk = (tid & 1) * 2;
    const __half* APtr[2];
#pragma unroll
    for (int it = 0; it < 2; it++)
        APtr[it] = A + (size_t)(m0 + arow) * K + (achk + it) * 8;

    const int brow = tid >> 1, bchk = (tid & 1) * 2;
    const __half* BPtr[4];
    {
        const __half* W = B;
        int nbase = n0;
        if (MODE == 4) {
            int region = n0 >> 10; nbase = n0 & 1023;
            W = (region == 0) ? B : (region == 1) ? B2 : B3;
        }
#pragma unroll
        for (int rt = 0; rt < 2; rt++)
#pragma unroll
            for (int jt = 0; jt < 2; jt++)
                BPtr[rt * 2 + jt] = W + (size_t)(nbase + brow + rt * 128) * K
                                      + (bchk + jt) * 8;
    }

    const uint32_t stAoff = ssu + (arow * LDTH + achk * 8) * 2;
    const uint32_t stBoff = ssu + STG_A * 2 + (brow * LDTH + bchk * 8) * 2;

    const int niter = K >> 5;

#pragma unroll
    for (int s = 0; s < 2; s++) {
        uint32_t off = s * STG_T * 2;
        int ko = s * BK;
#pragma unroll
        for (int it = 0; it < 2; it++)
            cp16(stAoff + off + it * 16, APtr[it] + ko);
#pragma unroll
        for (int rt = 0; rt < 2; rt++)
#pragma unroll
            for (int jt = 0; jt < 2; jt++)
                cp16(stBoff + off + rt * 128 * LDTH * 2 + jt * 16,
                     BPtr[rt * 2 + jt] + ko);
        CP_COMMIT();
    }

    float c[4][8][4] = {};

    const int r15 = lane & 15;
    const int ch16 = (lane >> 4) << 4;
    const uint32_t aAddr0 = (uint32_t)((wm * 64 + r15) * LDTH * 2 + ch16);
    const uint32_t bAddr0 = (uint32_t)(STG_A * 2 + (wn * 64 + r15) * LDTH * 2 + ch16);

    int bufc = 0;
    for (int i = 0; i < niter; i++) {
        CP_WAIT1();
        __syncthreads();

        int nb = i + 2;
        if (nb < niter) {
            int bufn = bufc + 2; if (bufn >= 3) bufn -= 3;
            uint32_t off = bufn * STG_T * 2;
            int ko = nb * BK;
#pragma unroll
            for (int it = 0; it < 2; it++)
                cp16(stAoff + off + it * 16, APtr[it] + ko);
#pragma unroll
            for (int rt = 0; rt < 2; rt++)
#pragma unroll
                for (int jt = 0; jt < 2; jt++)
                    cp16(stBoff + off + rt * 128 * LDTH * 2 + jt * 16,
                         BPtr[rt * 2 + jt] + ko);
        }
        CP_COMMIT();

        const uint32_t stA = ssu + bufc * STG_T * 2 + aAddr0;
        const uint32_t stB = ssu + bufc * STG_T * 2 + bAddr0;
#pragma unroll
        for (int ks = 0; ks < 2; ks++) {
            uint32_t af[4][4], bf[4][4];
#pragma unroll
            for (int mi = 0; mi < 4; mi++)
                ldsm4(af[mi], stA + mi * 16 * LDTH * 2 + ks * 32);
#pragma unroll
            for (int grp = 0; grp < 4; grp++)
                ldsm4(bf[grp], stB + grp * 16 * LDTH * 2 + ks * 32);
#pragma unroll
            for (int mi = 0; mi < 4; mi++)
#pragma unroll
                for (int ni = 0; ni < 8; ni++) {
                    int grp = ni >> 1, odd = ni & 1;
                    mma_f16(c[mi][ni], af[mi], bf[grp][odd], bf[grp][2 + odd]);
                }
        }
        if (++bufc == 3) bufc = 0;
    }

    if (MODE == 0) {
        float* C = (float*)Cv0;
#pragma unroll
        for (int mi = 0; mi < 4; mi++) {
            int r = m0 + wm * 64 + mi * 16 + g;
#pragma unroll
            for (int ni = 0; ni < 8; ni++) {
                int cc = n0 + wn * 64 + ni * 8 + tg * 2;
                size_t o1 = (size_t)r * N + cc;
                size_t o2 = (size_t)(r + 8) * N + cc;
                float2 v1 = make_float2(c[mi][ni][0], c[mi][ni][1]);
                float2 v2 = make_float2(c[mi][ni][2], c[mi][ni][3]);
                if (res) {
                    float2 r1 = *reinterpret_cast<const float2*>(res + o1);
                    float2 r2 = *reinterpret_cast<const float2*>(res + o2);
                    v1.x += r1.x; v1.y += r1.y; v2.x += r2.x; v2.y += r2.y;
                }
                *reinterpret_cast<float2*>(C + o1) = v1;
                *reinterpret_cast<float2*>(C + o2) = v2;
            }
        }
    } else if (MODE == 4) {
        int region = n0 >> 10, nloc = n0 & 1023;
        __half* OUT = (region == 0) ? (__half*)Cv0 : (region == 1) ? (__half*)Cv1 : (__half*)Cv2;
        int h = (nloc + wn * 64) >> 6;
        bool doRope = (region < 2);
#pragma unroll
        for (int mi = 0; mi < 4; mi++) {
#pragma unroll
            for (int half_ = 0; half_ < 2; half_++) {
                int r = m0 + wm * 64 + mi * 16 + g + half_ * 8;
                int bb = r >> 11, s = r & 2047;
                size_t base = (((size_t)(bb * NHEAD + h)) * SEQ + s) * 64;
                if (!doRope) {
#pragma unroll
                    for (int ni = 0; ni < 8; ni++) {
                        __half2 v = __floats2half2_rn(c[mi][ni][half_*2], c[mi][ni][half_*2+1]);
                        *reinterpret_cast<__half2*>(OUT + base + ni * 8 + tg * 2) = v;
                    }
                } else {
#pragma unroll
                    for (int ni = 0; ni < 4; ni++) {
                        int dk0 = ni * 8 + tg * 2;
                        float o1x, o1y, o2x, o2y;
#pragma unroll
                        for (int j = 0; j < 2; j++) {
                            int dk = dk0 + j;
                            float x1 = c[mi][ni][half_*2 + j];
                            float x2 = c[mi][ni+4][half_*2 + j];
                            float cs = g_cos[s * 32 + dk];
                            float sn = g_sin[s * 32 + dk];
                            float v1 = x1 * cs - x2 * sn;
                            float v2 = x2 * cs + x1 * sn;
                            if (j == 0) { o1x = v1; o2x = v2; }
                            else        { o1y = v1; o2y = v2; }
                        }
                        *reinterpret_cast<__half2*>(OUT + base + dk0)      = __floats2half2_rn(o1x, o1y);
                        *reinterpret_cast<__half2*>(OUT + base + dk0 + 32) = __floats2half2_rn(o2x, o2y);
                    }
                }
            }
        }
    } else {  // MODE 3
        __half* C = (__half*)Cv0;
        const int NO = N >> 1;
#pragma unroll
        for (int mi = 0; mi < 4; mi++) {
            int r = m0 + wm * 64 + mi * 16 + g;
#pragma unroll
            for (int ni = 0; ni < 8; ni++) {
                int oc = (n0 + wn * 64 + ni * 8) / 2 + tg;
                float u1a = c[mi][ni][0], u2a = c[mi][ni][1];
                float u1b = c[mi][ni][2], u2b = c[mi][ni][3];
                C[(size_t)r * NO + oc]       = __float2half_rn(u1a * (u2a / (1.0f + expf(-u2a))));
                C[(size_t)(r + 8) * NO + oc] = __float2half_rn(u1b * (u2b / (1.0f + expf(-u2b))));
            }
        }
    }
}

// ----------------------------------------------------------------------------
// Flash attention fp16, causal. 128-row q-tiles, warp = 16 rows x ALL 64 cols.
// Register-only softmax (warp-local) + register P pass (C-frag == next A-frag).
// smem: Q 128x72 | K 2x64x72 | V 2x64x72 halves = 55296 B. One barrier per tile.
// ----------------------------------------------------------------------------
#define LDH 72
#define KTI (64*LDH)                 // 4608 halves
#define QTI2 (128*LDH)               // 9216 halves
#define FA_SMEM ((QTI2 + 4*KTI)*2)   // 55296 bytes

__global__ void __launch_bounds__(256, 2) flash_attn_tc(
    const __half* __restrict__ Q, const __half* __restrict__ Kg,
    const __half* __restrict__ Vg, __half* __restrict__ ctx)
{
    extern __shared__ char fsc[];
    __half* Qs = (__half*)fsc;
    const uint32_t qsu = smem_u32(Qs);
    const uint32_t ksu = qsu + QTI2 * 2;
    const uint32_t vsu = ksu + 2 * KTI * 2;

    const int qt = (int)gridDim.x - 1 - (int)blockIdx.x;   // heavy first
    const int bh = blockIdx.y;
    const int tid = threadIdx.x;
    const int wm = tid >> 5;                // warp id = m-block (8 warps x 16 rows)
    const int lane = tid & 31;
    const int g = lane >> 2, tg = lane & 3;
    const int r15 = lane & 15;
    const int ch16 = (lane >> 4) << 4;

    const int qbase = qt * 128;
    const int rA = wm * 16 + g;             // local row (first of pair)
    const int qgA = qbase + rA, qgB = qgA + 8;

    // Q load: 128 rows x 8 x 16B chunks = 1024; 4 per thread (plain vector loads)
    const size_t baseQ = ((size_t)bh * SEQ + (size_t)qbase) * DHEAD;
#pragma unroll
    for (int it = 0; it < 4; it++) {
        int idx = tid + it * 256;
        int r = idx >> 3, c8 = (idx & 7) * 8;
        *reinterpret_cast<uint4*>(Qs + r * LDH + c8) =
            *reinterpret_cast<const uint4*>(Q + baseQ + (size_t)r * DHEAD + c8);
    }

    const int ntile = 2 * qt + 2;

    // prefetch kv tile 0 into buffer 0
    {
        const __half* Kb = Kg + ((size_t)bh * SEQ) * DHEAD;
        const __half* Vb = Vg + ((size_t)bh * SEQ) * DHEAD;
#pragma unroll
        for (int it = 0; it < 2; it++) {
            int idx = tid + it * 256;
            int r = idx >> 3, c8 = (idx & 7) * 8;
            cp16(ksu + (r * LDH + c8) * 2, Kb + (size_t)r * DHEAD + c8);
            cp16(vsu + (r * LDH + c8) * 2, Vb + (size_t)r * DHEAD + c8);
        }
        CP_COMMIT();
    }

    float co[8][4] = {};
    float rmA = -1e30f, rlA = 0.f, rmB = -1e30f, rlB = 0.f;

    for (int kt = 0; kt < ntile; kt++) {
        const int buf = kt & 1;
        CP_WAIT0();
        __syncthreads();                    // kv[buf] ready; kv[buf^1] free

        if (kt + 1 < ntile) {
            const __half* Kb = Kg + ((size_t)bh * SEQ + (size_t)(kt+1) * 64) * DHEAD;
            const __half* Vb = Vg + ((size_t)bh * SEQ + (size_t)(kt+1) * 64) * DHEAD;
            uint32_t kd = ksu + ((buf ^ 1) * KTI) * 2;
            uint32_t vd = vsu + ((buf ^ 1) * KTI) * 2;
#pragma unroll
            for (int it = 0; it < 2; it++) {
                int idx = tid + it * 256;
                int r = idx >> 3, c8 = (idx & 7) * 8;
                cp16(kd + (r * LDH + c8) * 2, Kb + (size_t)r * DHEAD + c8);
                cp16(vd + (r * LDH + c8) * 2, Vb + (size_t)r * DHEAD + c8);
            }
            CP_COMMIT();
        }

        const int kb = kt * 64;
        if (kb > qbase + wm * 16 + 15) continue;   // fully masked for this warp

        // ---- S = Q @ K^T : warp covers 16 rows x 64 cols ----
        float cs_[8][4] = {};
        {
            const uint32_t aQ = qsu + ((wm * 16 + r15) * LDH) * 2 + ch16;
            const uint32_t bK = ksu + (buf * KTI) * 2 + (r15 * LDH) * 2 + ch16;
#pragma unroll
            for (int ks = 0; ks < 4; ks++) {
                uint32_t qa[4];
                ldsm4(qa, aQ + ks * 32);
#pragma unroll
                for (int nc = 0; nc < 4; nc++) {
                    uint32_t kf[4];
                    ldsm4(kf, bK + nc * 16 * LDH * 2 + ks * 32);
                    mma_f16(cs_[nc*2],   qa, kf[0], kf[2]);
                    mma_f16(cs_[nc*2+1], qa, kf[1], kf[3]);
                }
            }
        }

        // ---- scale + causal mask ----
#pragma unroll
        for (int ni = 0; ni < 8; ni++)
#pragma unroll
            for (int jj = 0; jj < 4; jj++) cs_[ni][jj] *= 0.125f;
        if (kb + 63 > qbase + wm * 16) {
#pragma unroll
            for (int ni = 0; ni < 8; ni++) {
                int kg = kb + ni * 8 + 2 * tg;
                if (kg     > qgA) cs_[ni][0] = -1e30f;
                if (kg + 1 > qgA) cs_[ni][1] = -1e30f;
                if (kg     > qgB) cs_[ni][2] = -1e30f;
                if (kg + 1 > qgB) cs_[ni][3] = -1e30f;
            }
        }

        // ---- warp-local online softmax (registers only) ----
        {
            float mA = -1e30f, mB = -1e30f;
#pragma unroll
            for (int ni = 0; ni < 8; ni++) {
                mA = fmaxf(mA, fmaxf(cs_[ni][0], cs_[ni][1]));
                mB = fmaxf(mB, fmaxf(cs_[ni][2], cs_[ni][3]));
            }
            mA = fmaxf(mA, __shfl_xor_sync(0xffffffffu, mA, 1));
            mA = fmaxf(mA, __shfl_xor_sync(0xffffffffu, mA, 2));
            mB = fmaxf(mB, __shfl_xor_sync(0xffffffffu, mB, 1));
            mB = fmaxf(mB, __shfl_xor_sync(0xffffffffu, mB, 2));
            float mnA = fmaxf(rmA, mA), mnB = fmaxf(rmB, mB);
            float scA = __expf(rmA - mnA), scB = __expf(rmB - mnB);
            float lA = 0.f, lB = 0.f;
#pragma unroll
            for (int ni = 0; ni < 8; ni++) {
                cs_[ni][0] = __expf(cs_[ni][0] - mnA);
                cs_[ni][1] = __expf(cs_[ni][1] - mnA);
                cs_[ni][2] = __expf(cs_[ni][2] - mnB);
                cs_[ni][3] = __expf(cs_[ni][3] - mnB);
                lA += cs_[ni][0] + cs_[ni][1];
                lB += cs_[ni][2] + cs_[ni][3];
            }
            lA += __shfl_xor_sync(0xffffffffu, lA, 1);
            lA += __shfl_xor_sync(0xffffffffu, lA, 2);
            lB += __shfl_xor_sync(0xffffffffu, lB, 1);
            lB += __shfl_xor_sync(0xffffffffu, lB, 2);
            rlA = rlA * scA + lA; rmA = mnA;
            rlB = rlB * scB + lB; rmB = mnB;
#pragma unroll
            for (int ni = 0; ni < 8; ni++) {
                co[ni][0] *= scA; co[ni][1] *= scA;
                co[ni][2] *= scB; co[ni][3] *= scB;
            }
        }

        // ---- O += P @ V : P re-packed from registers (C-frag == A-frag) ----
        {
            const uint32_t vB = vsu + (buf * KTI) * 2 + ch16;
#pragma unroll
            for (int ks = 0; ks < 4; ks++) {
                uint32_t pa[4];
                pa[0] = packh2(cs_[2*ks][0],   cs_[2*ks][1]);
                pa[1] = packh2(cs_[2*ks][2],   cs_[2*ks][3]);
                pa[2] = packh2(cs_[2*ks+1][0], cs_[2*ks+1][1]);
                pa[3] = packh2(cs_[2*ks+1][2], cs_[2*ks+1][3]);
                uint32_t vrow = vB + ((ks * 16 + r15) * LDH) * 2;
#pragma unroll
                for (int nc = 0; nc < 4; nc++) {
                    uint32_t vf[4];
                    ldsm4t(vf, vrow + nc * 32);
                    mma_f16(co[nc*2],   pa, vf[0], vf[1]);
                    mma_f16(co[nc*2+1], pa, vf[2], vf[3]);
                }
            }
        }
    }

    // ---- final write (half) ----
    {
        int b = bh >> 4, h = bh & 15;
        float ilA = 1.0f / rlA, ilB = 1.0f / rlB;
#pragma unroll
        for (int half_ = 0; half_ < 2; half_++) {
            int row = qbase + wm * 16 + g + half_ * 8;
            float il = half_ ? ilB : ilA;
            size_t grow = ((size_t)b * SEQ + row) * DMODEL + h * 64;
#pragma unroll
            for (int ni = 0; ni < 8; ni++) {
                int d0 = ni * 8 + tg * 2;
                *reinterpret_cast<__half2*>(ctx + grow + d0) =
                    __floats2half2_rn(co[ni][half_*2] * il, co[ni][half_*2+1] * il);
            }
        }
    }
}

// ----------------------------------------------------------------------------
// Launch
// ----------------------------------------------------------------------------
extern "C" void kernel_launch(void* const* d_in, const int* in_sizes, int n_in,
                              void* d_out, int out_size) {
    const float* x  = (const float*)d_in[0];
    const float* wq = (const float*)d_in[2];
    const float* wk = (const float*)d_in[3];
    const float* wv = (const float*)d_in[4];
    const float* wo = (const float*)d_in[5];
    const float* w1 = (const float*)d_in[6];
    const float* w2 = (const float*)d_in[7];
    const float* g1 = (const float*)d_in[8];
    const float* g2 = (const float*)d_in[9];
    float* out = (float*)d_out;

    static __half *p_h=nullptr,*p_q=nullptr,*p_k=nullptr,*p_v=nullptr,
                  *p_ctx=nullptr,*p_ffn=nullptr,
                  *p_wqh=nullptr,*p_wkh=nullptr,*p_wvh=nullptr,*p_woh=nullptr,
                  *p_w1h=nullptr,*p_w2h=nullptr;
    static float *p_x2=nullptr;
    if (!p_h) {
        cudaGetSymbolAddress((void**)&p_h,   g_h);
        cudaGetSymbolAddress((void**)&p_q,   g_q);
        cudaGetSymbolAddress((void**)&p_k,   g_k);
        cudaGetSymbolAddress((void**)&p_v,   g_v);
        cudaGetSymbolAddress((void**)&p_ctx, g_ctx);
        cudaGetSymbolAddress((void**)&p_x2,  g_x2);
        cudaGetSymbolAddress((void**)&p_ffn, g_ffn);
        cudaGetSymbolAddress((void**)&p_wqh, g_wqh);
        cudaGetSymbolAddress((void**)&p_wkh, g_wkh);
        cudaGetSymbolAddress((void**)&p_wvh, g_wvh);
        cudaGetSymbolAddress((void**)&p_woh, g_woh);
        cudaGetSymbolAddress((void**)&p_w1h, g_w1h);
        cudaGetSymbolAddress((void**)&p_w2h, g_w2h);
        cudaFuncSetAttribute(gemm_mma<0>, cudaFuncAttributeMaxDynamicSharedMemorySize, GEMM_SMEM);
        cudaFuncSetAttribute(gemm_mma<3>, cudaFuncAttributeMaxDynamicSharedMemorySize, GEMM_SMEM);
        cudaFuncSetAttribute(gemm_mma<4>, cudaFuncAttributeMaxDynamicSharedMemorySize, GEMM_SMEM);
        cudaFuncSetAttribute(flash_attn_tc, cudaFuncAttributeMaxDynamicSharedMemorySize, FA_SMEM);
    }

    build_rope_table<<<(SEQ * 32 + 255) / 256, 256>>>();

    // one-shot weight conversion (w1 permuted inside)
    cvt_all<<<(CVT_TOTAL + 255) / 256, 256>>>(
        (const float2*)wq, (const float2*)wk, (const float2*)wv, (const float2*)wo,
        (const float2*)w1, (const float2*)w2,
        (__half2*)p_wqh, (__half2*)p_wkh, (__half2*)p_wvh, (__half2*)p_woh,
        (__half2*)p_w1h, (__half2*)p_w2h);

    // --- attention sublayer ---
    rmsnorm_k<<<ROWS, 256>>>(x, g1, p_h);

    dim3 gqkv(3 * DMODEL / 256, ROWS / 128);   // (12, 32)
    gemm_mma<4><<<gqkv, 256, GEMM_SMEM>>>(p_h, p_wqh, p_wkh, p_wvh, nullptr,
                                          p_q, p_k, p_v, ROWS, 3 * DMODEL, DMODEL);

    flash_attn_tc<<<dim3(SEQ / 128, BATCH * NHEAD), 256, FA_SMEM>>>(p_q, p_k, p_v, p_ctx);

    dim3 gproj(DMODEL / 256, ROWS / 128);      // (4, 32)
    gemm_mma<0><<<gproj, 256, GEMM_SMEM>>>(p_ctx, p_woh, nullptr, nullptr, x,
                                           p_x2, nullptr, nullptr, ROWS, DMODEL, DMODEL);

    // --- FFN sublayer ---
    rmsnorm_k<<<ROWS, 256>>>(p_x2, g2, p_h);
    dim3 gup(2 * DFF / 256, ROWS / 128);       // (32, 32)
    gemm_mma<3><<<gup, 256, GEMM_SMEM>>>(p_h, p_w1h, nullptr, nullptr, nullptr,
                                         p_ffn, nullptr, nullptr, ROWS, 2 * DFF, DMODEL);
    dim3 gdown(DMODEL / 256, ROWS / 128);      // (4, 32)
    gemm_mma<0><<<gdown, 256, GEMM_SMEM>>>(p_ffn, p_w2h, nullptr, nullptr, p_x2,
                                           out, nullptr, nullptr, ROWS, DMODEL, DFF);
}